// round 1
// baseline (speedup 1.0000x reference)
#include <cuda_runtime.h>

#define THREADS 256
#define TILE_R  64
#define SVS     132   // padded row stride (floats) for sV/sH/sT: kills LDS bank conflicts

typedef unsigned long long u64;

__device__ __forceinline__ u64 pack2(float lo, float hi){
    u64 r; asm("mov.b64 %0, {%1,%2};" : "=l"(r) : "f"(lo), "f"(hi)); return r;
}
__device__ __forceinline__ void unpack2(u64 v, float& lo, float& hi){
    asm("mov.b64 {%0,%1}, %2;" : "=f"(lo), "=f"(hi) : "l"(v));
}
__device__ __forceinline__ u64 ffma2(u64 a, u64 b, u64 c){
    u64 d; asm("fma.rn.f32x2 %0, %1, %2, %3;" : "=l"(d) : "l"(a), "l"(b), "l"(c)); return d;
}

__device__ __forceinline__ float gelu_exact(float x){
    return 0.5f * x * (1.0f + erff(x * 0.70710678118654752440f));
}

// LayerNorm over one 128-row handled by a quad (4 consecutive threads).
// src4/dst4 point at the row base (16B aligned). addVec (may be null) is added first.
__device__ __forceinline__ void ln_pass(const float4* __restrict__ src4,
                                        const float* __restrict__ addVec,
                                        const float* __restrict__ g,
                                        const float* __restrict__ be,
                                        float4* __restrict__ dst4,
                                        int quad)
{
    float4 u[8];
    float sum = 0.f, sq = 0.f;
#pragma unroll
    for (int i = 0; i < 8; ++i){
        int f = i*4 + quad;
        float4 v = src4[f];
        if (addVec){
            int c = 4*f;
            v.x += addVec[c+0]; v.y += addVec[c+1];
            v.z += addVec[c+2]; v.w += addVec[c+3];
        }
        u[i] = v;
        sum += v.x + v.y + v.z + v.w;
        sq = fmaf(v.x, v.x, sq); sq = fmaf(v.y, v.y, sq);
        sq = fmaf(v.z, v.z, sq); sq = fmaf(v.w, v.w, sq);
    }
    sum += __shfl_down_sync(0xffffffffu, sum, 2, 4);
    sum += __shfl_down_sync(0xffffffffu, sum, 1, 4);
    sq  += __shfl_down_sync(0xffffffffu, sq , 2, 4);
    sq  += __shfl_down_sync(0xffffffffu, sq , 1, 4);
    sum = __shfl_sync(0xffffffffu, sum, 0, 4);
    sq  = __shfl_sync(0xffffffffu, sq , 0, 4);

    float m    = sum * 0.0078125f;                       // /128
    float rstd = rsqrtf(sq * 0.0078125f - m*m + 1e-5f);  // biased var, eps inside rsqrt
#pragma unroll
    for (int i = 0; i < 8; ++i){
        int f = i*4 + quad; int c = 4*f;
        float4 v = u[i], o;
        o.x = (v.x - m)*rstd*g[c+0] + be[c+0];
        o.y = (v.y - m)*rstd*g[c+1] + be[c+1];
        o.z = (v.z - m)*rstd*g[c+2] + be[c+2];
        o.w = (v.w - m)*rstd*g[c+3] + be[c+3];
        dst4[f] = o;
    }
}

extern "C" __global__ void __launch_bounds__(THREADS, 1)
tsal_kernel(const float* __restrict__ x,
            const float* __restrict__ bo_time, const float* __restrict__ bo_recv,
            const float* __restrict__ g1, const float* __restrict__ be1,
            const float* __restrict__ g2, const float* __restrict__ be2,
            const float* __restrict__ g3, const float* __restrict__ be3,
            const float* __restrict__ g4, const float* __restrict__ be4,
            const float* __restrict__ W1a, const float* __restrict__ b1a,
            const float* __restrict__ W2a, const float* __restrict__ b2a,
            const float* __restrict__ W1b, const float* __restrict__ b1b,
            const float* __restrict__ W2b, const float* __restrict__ b2b,
            float* __restrict__ out)
{
    extern __shared__ float sm[];
    float* sV = sm;                      // [64][132] current row vectors (v1 -> v2 -> v3)
    float* sH = sV + TILE_R*SVS;         // [64][132] gelu(hidden) chunk
    float* sT = sH + TILE_R*SVS;         // [64][132] residual + mlp output (pre-LN)
    float* sW = sT + TILE_R*SVS;         // [128][128] staged weight chunk
    float* par  = sW + 128*128;
    float* pBoT = par;          float* pBoR = par + 128;
    float* pG1  = par + 256;    float* pBe1 = par + 384;
    float* pG2  = par + 512;    float* pBe2 = par + 640;
    float* pG3  = par + 768;    float* pBe3 = par + 896;
    float* pG4  = par + 1024;   float* pBe4 = par + 1152;
    float* pB2a = par + 1280;   float* pB2b = par + 1408;
    float* pB1a = par + 1536;   // 512
    float* pB1b = par + 2048;   // 512

    const int tid = threadIdx.x;

    // stage all small parameter vectors in SMEM
    for (int i = tid; i < 128; i += THREADS){
        pBoT[i] = bo_time[i]; pBoR[i] = bo_recv[i];
        pG1[i] = g1[i]; pBe1[i] = be1[i];
        pG2[i] = g2[i]; pBe2[i] = be2[i];
        pG3[i] = g3[i]; pBe3[i] = be3[i];
        pG4[i] = g4[i]; pBe4[i] = be4[i];
        pB2a[i] = b2a[i]; pB2b[i] = b2b[i];
    }
    for (int i = tid; i < 512; i += THREADS){ pB1a[i] = b1a[i]; pB1b[i] = b1b[i]; }

    const int row  = tid >> 2;      // 0..63 (LN row mapping)
    const int quad = tid & 3;
    const size_t grow = (size_t)blockIdx.x * TILE_R + row;

    __syncthreads();

    // v1 = LN(x + bo_time; g1, be1)
    ln_pass((const float4*)(x + grow*128), pBoT, pG1, pBe1,
            (float4*)(sV + row*SVS), quad);

    // GEMM thread tiling: 16x16 thread grid, 4 rows x 8 cols per thread
    const int ty = tid >> 4, tx = tid & 15;
    const int r0 = ty * 4, n0 = tx * 8;

    for (int mlp = 0; mlp < 2; ++mlp){
        const float* W1  = mlp ? W1b  : W1a;
        const float* W2  = mlp ? W2b  : W2a;
        const float* pB1 = mlp ? pB1b : pB1a;
        const float* pB2 = mlp ? pB2b : pB2a;

        u64 acc2[4][4];
#pragma unroll
        for (int i = 0; i < 4; ++i)
#pragma unroll
            for (int j = 0; j < 4; ++j) acc2[i][j] = 0ull;

        for (int nc = 0; nc < 4; ++nc){
            __syncthreads();  // protect sW reuse + (first iter) sV readiness
            // stage W1 chunk: W1[k][nc*128 .. +127], k = 0..127
#pragma unroll
            for (int t = 0; t < 16; ++t){
                int lin = tid + t*THREADS;           // float4 unit index, 0..4095
                int k = lin >> 5, c4 = lin & 31;
                ((float4*)sW)[lin] =
                    ((const float4*)(W1 + (size_t)k*512 + nc*128))[c4];
            }
            __syncthreads();

            // GEMM1: Hc[64x128] = sV(64x128) @ sW(128x128)
            u64 acc1[4][4];
#pragma unroll
            for (int i = 0; i < 4; ++i)
#pragma unroll
                for (int j = 0; j < 4; ++j) acc1[i][j] = 0ull;

#pragma unroll 4
            for (int k = 0; k < 128; ++k){
                u64 ad[4];
#pragma unroll
                for (int i = 0; i < 4; ++i){
                    float a = sV[(r0+i)*SVS + k];
                    ad[i] = pack2(a, a);
                }
                const ulonglong2* bw = (const ulonglong2*)(sW + k*128 + n0);
                ulonglong2 p0 = bw[0], p1 = bw[1];
#pragma unroll
                for (int i = 0; i < 4; ++i){
                    acc1[i][0] = ffma2(ad[i], p0.x, acc1[i][0]);
                    acc1[i][1] = ffma2(ad[i], p0.y, acc1[i][1]);
                    acc1[i][2] = ffma2(ad[i], p1.x, acc1[i][2]);
                    acc1[i][3] = ffma2(ad[i], p1.y, acc1[i][3]);
                }
            }

            // bias + exact GELU -> sH
#pragma unroll
            for (int i = 0; i < 4; ++i){
                float h[8];
#pragma unroll
                for (int j = 0; j < 4; ++j) unpack2(acc1[i][j], h[2*j], h[2*j+1]);
#pragma unroll
                for (int j = 0; j < 8; ++j)
                    h[j] = gelu_exact(h[j] + pB1[nc*128 + n0 + j]);
                float4* d = (float4*)(sH + (r0+i)*SVS + n0);
                d[0] = make_float4(h[0],h[1],h[2],h[3]);
                d[1] = make_float4(h[4],h[5],h[6],h[7]);
            }
            __syncthreads();

            // stage W2 chunk: rows j = nc*128..+127, 128 cols each (contiguous)
#pragma unroll
            for (int t = 0; t < 16; ++t){
                int lin = tid + t*THREADS;
                int k = lin >> 5, c4 = lin & 31;
                ((float4*)sW)[lin] =
                    ((const float4*)(W2 + (size_t)(nc*128 + k)*128))[c4];
            }
            __syncthreads();

            // GEMM2 (accumulate): T += Hc(64x128) @ sW(128x128)
#pragma unroll 4
            for (int k = 0; k < 128; ++k){
                u64 ad[4];
#pragma unroll
                for (int i = 0; i < 4; ++i){
                    float a = sH[(r0+i)*SVS + k];
                    ad[i] = pack2(a, a);
                }
                const ulonglong2* bw = (const ulonglong2*)(sW + k*128 + n0);
                ulonglong2 p0 = bw[0], p1 = bw[1];
#pragma unroll
                for (int i = 0; i < 4; ++i){
                    acc2[i][0] = ffma2(ad[i], p0.x, acc2[i][0]);
                    acc2[i][1] = ffma2(ad[i], p0.y, acc2[i][1]);
                    acc2[i][2] = ffma2(ad[i], p1.x, acc2[i][2]);
                    acc2[i][3] = ffma2(ad[i], p1.y, acc2[i][3]);
                }
            }
        } // nc chunks

        // epilogue: pre-LN = residual(sV) + mlp_out + b2
#pragma unroll
        for (int i = 0; i < 4; ++i){
            float t0[8];
#pragma unroll
            for (int j = 0; j < 4; ++j) unpack2(acc2[i][j], t0[2*j], t0[2*j+1]);
            int r = r0 + i;
#pragma unroll
            for (int j = 0; j < 8; ++j){
                int c = n0 + j;
                sT[r*SVS + c] = sV[r*SVS + c] + t0[j] + pB2[c];
            }
        }
        __syncthreads();

        if (mlp == 0){
            // v2 = LN(v1 + mlp1; g2, be2)
            ln_pass((const float4*)(sT + row*SVS), nullptr, pG2, pBe2,
                    (float4*)(sV + row*SVS), quad);
            // v3 = LN(v2 + bo_recv; g3, be3)   (same elements, same thread -> no sync needed)
            ln_pass((const float4*)(sV + row*SVS), pBoR, pG3, pBe3,
                    (float4*)(sV + row*SVS), quad);
        } else {
            // out = LN(v3 + mlp2; g4, be4)  -> straight to GMEM
            ln_pass((const float4*)(sT + row*SVS), nullptr, pG4, pBe4,
                    (float4*)(out + grow*128), quad);
        }
    }
}

extern "C" void kernel_launch(void* const* d_in, const int* in_sizes, int n_in,
                              void* d_out, int out_size)
{
    const float* x       = (const float*)d_in[0];
    // d_in[1] = router (dead), d_in[3] = bo_send (dead)
    const float* bo_time = (const float*)d_in[2];
    const float* bo_recv = (const float*)d_in[4];
    const float* g1 = (const float*)d_in[5],  *be1 = (const float*)d_in[6];
    const float* g2 = (const float*)d_in[7],  *be2 = (const float*)d_in[8];
    const float* g3 = (const float*)d_in[9],  *be3 = (const float*)d_in[10];
    const float* g4 = (const float*)d_in[11], *be4 = (const float*)d_in[12];
    const float* W1a = (const float*)d_in[13], *b1a = (const float*)d_in[14];
    const float* W2a = (const float*)d_in[15], *b2a = (const float*)d_in[16];
    const float* W1b = (const float*)d_in[17], *b1b = (const float*)d_in[18];
    const float* W2b = (const float*)d_in[19], *b2b = (const float*)d_in[20];
    float* out = (float*)d_out;

    int rows   = in_sizes[0] / 128;    // 131072
    int blocks = rows / TILE_R;        // 2048
    size_t shmem = (size_t)(3*TILE_R*SVS + 128*128 + 2560) * sizeof(float); // 177152 B

    cudaFuncSetAttribute(tsal_kernel,
                         cudaFuncAttributeMaxDynamicSharedMemorySize, (int)shmem);

    tsal_kernel<<<blocks, THREADS, shmem>>>(
        x, bo_time, bo_recv,
        g1, be1, g2, be2, g3, be3, g4, be4,
        W1a, b1a, W2a, b2a, W1b, b1b, W2b, b2b,
        out);
}

// round 2
// speedup vs baseline: 1.5154x; 1.5154x over previous
#include <cuda_runtime.h>

#define THREADS 256
#define TILE_R  128
#define SVS     132   // padded row stride (floats) for sV/sH

typedef unsigned long long u64;

__device__ __forceinline__ u64 pack2(float lo, float hi){
    u64 r; asm("mov.b64 %0, {%1,%2};" : "=l"(r) : "f"(lo), "f"(hi)); return r;
}
__device__ __forceinline__ void unpack2(u64 v, float& lo, float& hi){
    asm("mov.b64 {%0,%1}, %2;" : "=f"(lo), "=f"(hi) : "l"(v));
}
__device__ __forceinline__ u64 ffma2(u64 a, u64 b, u64 c){
    u64 d; asm("fma.rn.f32x2 %0, %1, %2, %3;" : "=l"(d) : "l"(a), "l"(b), "l"(c)); return d;
}

__device__ __forceinline__ float gelu_exact(float x){
    return 0.5f * x * (1.0f + erff(x * 0.70710678118654752440f));
}

// Two-pass LayerNorm over one 128-float row, handled by a PAIR of threads
// (adjacent lanes). half selects which 64 floats this thread owns.
// addVec (may be null) is added to src before normalization.
__device__ __forceinline__ void ln_row(const float4* __restrict__ src4,
                                       const float* __restrict__ addVec,
                                       const float* __restrict__ g,
                                       const float* __restrict__ be,
                                       float4* __restrict__ dst4,
                                       int half)
{
    float sum = 0.f, sq = 0.f;
#pragma unroll
    for (int i = 0; i < 16; ++i){
        int f = half*16 + i;
        float4 v = src4[f];
        if (addVec){
            int c = 4*f;
            v.x += addVec[c+0]; v.y += addVec[c+1];
            v.z += addVec[c+2]; v.w += addVec[c+3];
        }
        sum += v.x + v.y + v.z + v.w;
        sq = fmaf(v.x, v.x, sq); sq = fmaf(v.y, v.y, sq);
        sq = fmaf(v.z, v.z, sq); sq = fmaf(v.w, v.w, sq);
    }
    sum += __shfl_xor_sync(0xffffffffu, sum, 1, 2);
    sq  += __shfl_xor_sync(0xffffffffu, sq , 1, 2);

    float m    = sum * 0.0078125f;                       // /128
    float rstd = rsqrtf(sq * 0.0078125f - m*m + 1e-5f);  // biased var
#pragma unroll
    for (int i = 0; i < 16; ++i){
        int f = half*16 + i; int c = 4*f;
        float4 v = src4[f];
        if (addVec){
            v.x += addVec[c+0]; v.y += addVec[c+1];
            v.z += addVec[c+2]; v.w += addVec[c+3];
        }
        float4 o;
        o.x = (v.x - m)*rstd*g[c+0] + be[c+0];
        o.y = (v.y - m)*rstd*g[c+1] + be[c+1];
        o.z = (v.z - m)*rstd*g[c+2] + be[c+2];
        o.w = (v.w - m)*rstd*g[c+3] + be[c+3];
        dst4[f] = o;
    }
}

extern "C" __global__ void __launch_bounds__(THREADS, 1)
tsal_kernel(const float* __restrict__ x,
            const float* __restrict__ bo_time, const float* __restrict__ bo_recv,
            const float* __restrict__ g1, const float* __restrict__ be1,
            const float* __restrict__ g2, const float* __restrict__ be2,
            const float* __restrict__ g3, const float* __restrict__ be3,
            const float* __restrict__ g4, const float* __restrict__ be4,
            const float* __restrict__ W1a, const float* __restrict__ b1a,
            const float* __restrict__ W2a, const float* __restrict__ b2a,
            const float* __restrict__ W1b, const float* __restrict__ b1b,
            const float* __restrict__ W2b, const float* __restrict__ b2b,
            float* __restrict__ out)
{
    extern __shared__ float sm[];
    float* sV = sm;                      // [128][132] current row vectors
    float* sH = sV + TILE_R*SVS;         // [128][132] gelu(hidden) chunk; later pre-LN T
    float* sW = sH + TILE_R*SVS;         // [128][128] staged weight chunk
    float* par  = sW + 128*128;
    float* pBoT = par;          float* pBoR = par + 128;
    float* pG1  = par + 256;    float* pBe1 = par + 384;
    float* pG2  = par + 512;    float* pBe2 = par + 640;
    float* pG3  = par + 768;    float* pBe3 = par + 896;
    float* pG4  = par + 1024;   float* pBe4 = par + 1152;
    float* pB2a = par + 1280;   float* pB2b = par + 1408;
    float* pB1a = par + 1536;   // 512
    float* pB1b = par + 2048;   // 512

    const int tid = threadIdx.x;

    for (int i = tid; i < 128; i += THREADS){
        pBoT[i] = bo_time[i]; pBoR[i] = bo_recv[i];
        pG1[i] = g1[i]; pBe1[i] = be1[i];
        pG2[i] = g2[i]; pBe2[i] = be2[i];
        pG3[i] = g3[i]; pBe3[i] = be3[i];
        pG4[i] = g4[i]; pBe4[i] = be4[i];
        pB2a[i] = b2a[i]; pB2b[i] = b2b[i];
    }
    for (int i = tid; i < 512; i += THREADS){ pB1a[i] = b1a[i]; pB1b[i] = b1b[i]; }

    const int row  = tid >> 1;      // 0..127 (LN row mapping, 2 threads/row)
    const int half = tid & 1;
    const size_t grow = (size_t)blockIdx.x * TILE_R + row;

    __syncthreads();

    // v1 = LN(x + bo_time; g1, be1)
    ln_row((const float4*)(x + grow*128), pBoT, pG1, pBe1,
           (float4*)(sV + row*SVS), half);

    // GEMM thread tiling: 16x16 thread grid, 8 rows x 8 cols per thread
    const int ty = tid >> 4, tx = tid & 15;
    const int r0 = ty * 8, n0 = tx * 8;

    for (int mlp = 0; mlp < 2; ++mlp){
        const float* W1  = mlp ? W1b  : W1a;
        const float* W2  = mlp ? W2b  : W2a;
        const float* pB1 = mlp ? pB1b : pB1a;
        const float* pB2 = mlp ? pB2b : pB2a;

        u64 acc2[8][4];
#pragma unroll
        for (int i = 0; i < 8; ++i)
#pragma unroll
            for (int j = 0; j < 4; ++j) acc2[i][j] = 0ull;

        for (int nc = 0; nc < 4; ++nc){
            __syncthreads();  // sW safe to overwrite; (first iter) sV ready
            // stage W1 chunk: W1[k][nc*128 .. +127], k = 0..127
#pragma unroll
            for (int t = 0; t < 16; ++t){
                int lin = tid + t*THREADS;           // float4 index, 0..4095
                int k = lin >> 5, c4 = lin & 31;
                ((float4*)sW)[lin] =
                    ((const float4*)(W1 + (size_t)k*512 + nc*128))[c4];
            }
            __syncthreads();

            // GEMM1: Hc[128x128] = sV(128x128) @ sW(128x128)
            u64 acc1[8][4];
#pragma unroll
            for (int i = 0; i < 8; ++i)
#pragma unroll
                for (int j = 0; j < 4; ++j) acc1[i][j] = 0ull;

#pragma unroll 2
            for (int k2 = 0; k2 < 64; ++k2){
                float2 av[8];
#pragma unroll
                for (int i = 0; i < 8; ++i)
                    av[i] = *(const float2*)(sV + (r0+i)*SVS + k2*2);
#pragma unroll
                for (int kk = 0; kk < 2; ++kk){
                    const ulonglong2* bw =
                        (const ulonglong2*)(sW + (k2*2+kk)*128 + n0);
                    ulonglong2 p0 = bw[0], p1 = bw[1];
#pragma unroll
                    for (int i = 0; i < 8; ++i){
                        float a = kk ? av[i].y : av[i].x;
                        u64 ad = pack2(a, a);
                        acc1[i][0] = ffma2(ad, p0.x, acc1[i][0]);
                        acc1[i][1] = ffma2(ad, p0.y, acc1[i][1]);
                        acc1[i][2] = ffma2(ad, p1.x, acc1[i][2]);
                        acc1[i][3] = ffma2(ad, p1.y, acc1[i][3]);
                    }
                }
            }

            // bias + exact GELU -> sH
#pragma unroll
            for (int i = 0; i < 8; ++i){
                float h[8];
#pragma unroll
                for (int j = 0; j < 4; ++j) unpack2(acc1[i][j], h[2*j], h[2*j+1]);
#pragma unroll
                for (int j = 0; j < 8; ++j)
                    h[j] = gelu_exact(h[j] + pB1[nc*128 + n0 + j]);
                float4* d = (float4*)(sH + (r0+i)*SVS + n0);
                d[0] = make_float4(h[0],h[1],h[2],h[3]);
                d[1] = make_float4(h[4],h[5],h[6],h[7]);
            }
            __syncthreads();   // sH complete; sW (W1) reads done

            // stage W2 chunk: rows j = nc*128..+127 (contiguous 128 cols)
#pragma unroll
            for (int t = 0; t < 16; ++t){
                int lin = tid + t*THREADS;
                int k = lin >> 5, c4 = lin & 31;
                ((float4*)sW)[lin] =
                    ((const float4*)(W2 + (size_t)(nc*128 + k)*128))[c4];
            }
            __syncthreads();

            // GEMM2 (accumulate): T += Hc(128x128) @ sW(128x128)
#pragma unroll 2
            for (int k2 = 0; k2 < 64; ++k2){
                float2 av[8];
#pragma unroll
                for (int i = 0; i < 8; ++i)
                    av[i] = *(const float2*)(sH + (r0+i)*SVS + k2*2);
#pragma unroll
                for (int kk = 0; kk < 2; ++kk){
                    const ulonglong2* bw =
                        (const ulonglong2*)(sW + (k2*2+kk)*128 + n0);
                    ulonglong2 p0 = bw[0], p1 = bw[1];
#pragma unroll
                    for (int i = 0; i < 8; ++i){
                        float a = kk ? av[i].y : av[i].x;
                        u64 ad = pack2(a, a);
                        acc2[i][0] = ffma2(ad, p0.x, acc2[i][0]);
                        acc2[i][1] = ffma2(ad, p0.y, acc2[i][1]);
                        acc2[i][2] = ffma2(ad, p1.x, acc2[i][2]);
                        acc2[i][3] = ffma2(ad, p1.y, acc2[i][3]);
                    }
                }
            }
        } // nc chunks

        __syncthreads();   // all GEMM2 reads of sH done before overwriting with T

        // epilogue: pre-LN T = residual(sV) + mlp_out + b2 -> sH
#pragma unroll
        for (int i = 0; i < 8; ++i){
            float t0[8];
#pragma unroll
            for (int j = 0; j < 4; ++j) unpack2(acc2[i][j], t0[2*j], t0[2*j+1]);
            int r = r0 + i;
#pragma unroll
            for (int j = 0; j < 8; ++j){
                int c = n0 + j;
                sH[r*SVS + c] = sV[r*SVS + c] + t0[j] + pB2[c];
            }
        }
        __syncthreads();

        if (mlp == 0){
            // v2 = LN(T; g2, be2) -> sV
            ln_row((const float4*)(sH + row*SVS), nullptr, pG2, pBe2,
                   (float4*)(sV + row*SVS), half);
            // v3 = LN(v2 + bo_recv; g3, be3) -> sV (same thread, same elems)
            ln_row((const float4*)(sV + row*SVS), pBoR, pG3, pBe3,
                   (float4*)(sV + row*SVS), half);
        } else {
            // out = LN(T; g4, be4) -> GMEM
            ln_row((const float4*)(sH + row*SVS), nullptr, pG4, pBe4,
                   (float4*)(out + grow*128), half);
        }
    }
}

extern "C" void kernel_launch(void* const* d_in, const int* in_sizes, int n_in,
                              void* d_out, int out_size)
{
    const float* x       = (const float*)d_in[0];
    // d_in[1] = router (dead), d_in[3] = bo_send (dead)
    const float* bo_time = (const float*)d_in[2];
    const float* bo_recv = (const float*)d_in[4];
    const float* g1 = (const float*)d_in[5],  *be1 = (const float*)d_in[6];
    const float* g2 = (const float*)d_in[7],  *be2 = (const float*)d_in[8];
    const float* g3 = (const float*)d_in[9],  *be3 = (const float*)d_in[10];
    const float* g4 = (const float*)d_in[11], *be4 = (const float*)d_in[12];
    const float* W1a = (const float*)d_in[13], *b1a = (const float*)d_in[14];
    const float* W2a = (const float*)d_in[15], *b2a = (const float*)d_in[16];
    const float* W1b = (const float*)d_in[17], *b1b = (const float*)d_in[18];
    const float* W2b = (const float*)d_in[19], *b2b = (const float*)d_in[20];
    float* out = (float*)d_out;

    int rows   = in_sizes[0] / 128;    // 131072
    int blocks = rows / TILE_R;        // 1024
    size_t shmem = (size_t)(2*TILE_R*SVS + 128*128 + 2560) * sizeof(float); // 211 KB

    cudaFuncSetAttribute(tsal_kernel,
                         cudaFuncAttributeMaxDynamicSharedMemorySize, (int)shmem);

    tsal_kernel<<<blocks, THREADS, shmem>>>(
        x, bo_time, bo_recv,
        g1, be1, g2, be2, g3, be3, g4, be4,
        W1a, b1a, W2a, b2a, W1b, b1b, W2b, b2b,
        out);
}

// round 4
// speedup vs baseline: 3.8721x; 2.5552x over previous
#include <cuda_runtime.h>
#include <cstdint>

#define THREADS 256
#define TILE_R  128
#define NCHUNK  8      // DFF=512 in n-chunks of 64
#define SVS     132    // padded row stride (floats); 132 mod 32 = 4 -> conflict-free gathers

// ---- SMEM float offsets ----
#define OFF_V   0                  // 128*132 = 16896
#define OFF_HT  16896              // 128*132 = 16896 (H chunk cols 0..63; later full T)
#define OFF_W0  33792              // 8192 (B-frag image buffer 0)
#define OFF_W1  41984              // 8192 (B-frag image buffer 1)
#define OFF_PAR 50176              // 2560
#define SMEM_FLOATS (50176 + 2560) // 52736 floats = 210944 bytes

// pre-packed B-fragment weight images (tf32-rounded):
// w1img[mlp][chunk]: GEMM1 B (K=128 x N=64): slot ((kt*8+nt)*32+lane) -> float2 (b0,b1)
// w2img[mlp][chunk]: GEMM2 B (K=64 x N=128): slot ((kt*16+nt)*32+lane) -> float2
__device__ float g_w1img[2][NCHUNK][8192];
__device__ float g_w2img[2][NCHUNK][8192];

__device__ __forceinline__ uint32_t smem_u32(const void* p){
    uint32_t a;
    asm("{ .reg .u64 t; cvta.to.shared.u64 t, %1; cvt.u32.u64 %0, t; }"
        : "=r"(a) : "l"(p));
    return a;
}
__device__ __forceinline__ uint32_t to_tf32(float f){
    uint32_t u; asm("cvt.rna.tf32.f32 %0, %1;" : "=r"(u) : "f"(f)); return u;
}
__device__ __forceinline__ float gelu_exact(float x){
    return 0.5f * x * (1.0f + erff(x * 0.70710678118654752440f));
}

#define MMA_TF32(d, a, b) asm volatile( \
    "mma.sync.aligned.m16n8k8.row.col.f32.tf32.tf32.f32 " \
    "{%0,%1,%2,%3},{%4,%5,%6,%7},{%8,%9},{%0,%1,%2,%3};" \
    : "+f"((d)[0]), "+f"((d)[1]), "+f"((d)[2]), "+f"((d)[3]) \
    : "r"((a)[0]), "r"((a)[1]), "r"((a)[2]), "r"((a)[3]), \
      "r"((b)[0]), "r"((b)[1]))

#define CP_ASYNC16(dst, src) asm volatile( \
    "cp.async.cg.shared.global [%0], [%1], 16;" :: "r"(dst), "l"(src))
#define CP_COMMIT() asm volatile("cp.async.commit_group;" ::: "memory")
#define CP_WAIT0()  asm volatile("cp.async.wait_group 0;" ::: "memory")

// stage a 32KB (8192-float) image into SMEM via cp.async (one commit group)
__device__ __forceinline__ void stage_img(uint32_t dstAddr, const float* src, int tid){
    const float4* s4 = (const float4*)src;
#pragma unroll
    for (int i = 0; i < 8; ++i)
        CP_ASYNC16(dstAddr + (uint32_t)(tid + i*THREADS)*16u, s4 + tid + i*THREADS);
    CP_COMMIT();
}

// Two-pass LayerNorm over one 128-float row, handled by a PAIR of threads.
__device__ __forceinline__ void ln_row(const float4* __restrict__ src4,
                                       const float* __restrict__ addVec,
                                       const float* __restrict__ g,
                                       const float* __restrict__ be,
                                       float4* __restrict__ dst4,
                                       int half)
{
    float sum = 0.f, sq = 0.f;
#pragma unroll
    for (int i = 0; i < 16; ++i){
        int f = half*16 + i;
        float4 v = src4[f];
        if (addVec){
            int c = 4*f;
            v.x += addVec[c+0]; v.y += addVec[c+1];
            v.z += addVec[c+2]; v.w += addVec[c+3];
        }
        sum += v.x + v.y + v.z + v.w;
        sq = fmaf(v.x, v.x, sq); sq = fmaf(v.y, v.y, sq);
        sq = fmaf(v.z, v.z, sq); sq = fmaf(v.w, v.w, sq);
    }
    sum += __shfl_xor_sync(0xffffffffu, sum, 1, 2);
    sq  += __shfl_xor_sync(0xffffffffu, sq , 1, 2);
    float m    = sum * 0.0078125f;
    float rstd = rsqrtf(sq * 0.0078125f - m*m + 1e-5f);
#pragma unroll
    for (int i = 0; i < 16; ++i){
        int f = half*16 + i; int c = 4*f;
        float4 v = src4[f];
        if (addVec){
            v.x += addVec[c+0]; v.y += addVec[c+1];
            v.z += addVec[c+2]; v.w += addVec[c+3];
        }
        float4 o;
        o.x = (v.x - m)*rstd*g[c+0] + be[c+0];
        o.y = (v.y - m)*rstd*g[c+1] + be[c+1];
        o.z = (v.z - m)*rstd*g[c+2] + be[c+2];
        o.w = (v.w - m)*rstd*g[c+3] + be[c+3];
        dst4[f] = o;
    }
}

// ---------------- prep: build tf32 B-fragment weight images ----------------
__global__ void prep_kernel(const float* __restrict__ W1a, const float* __restrict__ W2a,
                            const float* __restrict__ W1b, const float* __restrict__ W2b)
{
    int idx = blockIdx.x * 256 + threadIdx.x;      // 0 .. 131071
    int isW2 = (idx >> 16) & 1;
    int r = idx & 65535;
    int m = (r >> 15) & 1;
    int c = (r >> 12) & 7;
    int s = r & 4095;
    int lane = s & 31;
    if (!isW2){
        int kt = s >> 8, nt = (s >> 5) & 7;
        const float* W1 = m ? W1b : W1a;
        int row0 = kt*8 + (lane & 3);
        int col  = c*64 + nt*8 + (lane >> 2);
        float b0 = W1[(size_t)row0 * 512 + col];
        float b1 = W1[(size_t)(row0 + 4) * 512 + col];
        int slot = (kt*8 + nt)*32 + lane;
        g_w1img[m][c][slot*2 + 0] = __uint_as_float(to_tf32(b0));
        g_w1img[m][c][slot*2 + 1] = __uint_as_float(to_tf32(b1));
    } else {
        int kt = s >> 9, nt = (s >> 5) & 15;
        const float* W2 = m ? W2b : W2a;
        int row0 = c*64 + kt*8 + (lane & 3);
        int col  = nt*8 + (lane >> 2);
        float b0 = W2[(size_t)row0 * 128 + col];
        float b1 = W2[(size_t)(row0 + 4) * 128 + col];
        int slot = (kt*16 + nt)*32 + lane;
        g_w2img[m][c][slot*2 + 0] = __uint_as_float(to_tf32(b0));
        g_w2img[m][c][slot*2 + 1] = __uint_as_float(to_tf32(b1));
    }
}

// ---------------- main kernel ----------------
extern "C" __global__ void __launch_bounds__(THREADS, 1)
tsal_mma_kernel(const float* __restrict__ x,
                const float* __restrict__ bo_time, const float* __restrict__ bo_recv,
                const float* __restrict__ g1, const float* __restrict__ be1,
                const float* __restrict__ g2, const float* __restrict__ be2,
                const float* __restrict__ g3, const float* __restrict__ be3,
                const float* __restrict__ g4, const float* __restrict__ be4,
                const float* __restrict__ b1a, const float* __restrict__ b2a,
                const float* __restrict__ b1b, const float* __restrict__ b2b,
                float* __restrict__ out)
{
    extern __shared__ float sm[];
    float* sV  = sm + OFF_V;
    float* sHT = sm + OFF_HT;
    float* par = sm + OFF_PAR;
    const uint32_t wAddr[2] = { smem_u32(sm + OFF_W0), smem_u32(sm + OFF_W1) };
    float* const sWf[2] = { sm + OFF_W0, sm + OFF_W1 };

    const int tid  = threadIdx.x;
    const int wid  = tid >> 5, lane = tid & 31;
    const int wr   = wid & 3, wc = wid >> 2;     // warp grid 4x2
    const int lrow = tid >> 1, lhalf = tid & 1;  // LN mapping: 2 threads/row
    const int qrow = lane >> 2, qcol = lane & 3; // fragment quad coords

    // stage params
    for (int i = tid; i < 128; i += THREADS){
        par[i]        = bo_time[i]; par[128 + i]  = bo_recv[i];
        par[256 + i]  = g1[i];      par[384 + i]  = be1[i];
        par[512 + i]  = g2[i];      par[640 + i]  = be2[i];
        par[768 + i]  = g3[i];      par[896 + i]  = be3[i];
        par[1024 + i] = g4[i];      par[1152 + i] = be4[i];
        par[1280 + i] = b2a[i];     par[1408 + i] = b2b[i];
    }
    for (int i = tid; i < 512; i += THREADS){
        par[1536 + i] = b1a[i];     par[2048 + i] = b1b[i];
    }
    __syncthreads();   // params visible (LN1 reads them)

    // LN1: v1 = LN(x + bo_time) -> sV (row-major, fp32)
    const size_t grow = (size_t)blockIdx.x * TILE_R + lrow;
    ln_row((const float4*)(x + grow * 128), par /*bo_time*/, par + 256, par + 384,
           (float4*)(sV + lrow * SVS), lhalf);

    // prefetch W1 image chunk 0 of mlp 0
    stage_img(wAddr[0], &g_w1img[0][0][0], tid);

    for (int mlp = 0; mlp < 2; ++mlp){
        const float* pB1 = par + (mlp ? 2048 : 1536);
        const float* pB2 = par + (mlp ? 1408 : 1280);

        float acc2[2][8][4];
#pragma unroll
        for (int a = 0; a < 2; ++a)
#pragma unroll
            for (int b = 0; b < 8; ++b)
#pragma unroll
                for (int d = 0; d < 4; ++d) acc2[a][b][d] = 0.f;

        for (int ch = 0; ch < NCHUNK; ++ch){
            // W1[ch] must be resident in sW0; all prior phase reads/writes done
            CP_WAIT0();
            __syncthreads();
            // start fetching W2[ch] into sW1 (overlaps GEMM1)
            stage_img(wAddr[1], &g_w2img[mlp][ch][0], tid);

            // ---- GEMM1: H(128x64) = V(128x128) @ W1chunk ----
            float acc1[2][4][4];
#pragma unroll
            for (int a = 0; a < 2; ++a)
#pragma unroll
                for (int b = 0; b < 4; ++b)
#pragma unroll
                    for (int d = 0; d < 4; ++d) acc1[a][b][d] = 0.f;

            {
                const int m0 = wr*32 + qrow;
#pragma unroll 4
                for (int ks = 0; ks < 16; ++ks){
                    const int k0 = ks*8 + qcol;
                    uint32_t A[2][4];
#pragma unroll
                    for (int mt = 0; mt < 2; ++mt){
                        const float* vp = sV + (m0 + 16*mt)*SVS + k0;
                        A[mt][0] = to_tf32(vp[0]);
                        A[mt][1] = to_tf32(vp[8*SVS]);
                        A[mt][2] = to_tf32(vp[4]);
                        A[mt][3] = to_tf32(vp[8*SVS + 4]);
                    }
#pragma unroll
                    for (int ntl = 0; ntl < 4; ++ntl){
                        const float2 bf = *(const float2*)
                            (sWf[0] + ((ks*8 + wc*4 + ntl)*32 + lane)*2);
                        uint32_t B[2] = { __float_as_uint(bf.x), __float_as_uint(bf.y) };
                        MMA_TF32(acc1[0][ntl], A[0], B);
                        MMA_TF32(acc1[1][ntl], A[1], B);
                    }
                }
            }
            __syncthreads();   // all GEMM1 reads of sW0 + (c>0) GEMM2 reads of sHT done

            // kick off W1 chunk for next phase into sW0 (overlaps epilogue+GEMM2)
            if (ch < NCHUNK - 1)       stage_img(wAddr[0], &g_w1img[mlp][ch+1][0], tid);
            else if (mlp == 0)         stage_img(wAddr[0], &g_w1img[1][0][0], tid);

            // ---- epilogue: bias + exact GELU -> sHT cols 0..63 (tf32-rounded) ----
#pragma unroll
            for (int mt = 0; mt < 2; ++mt){
                const int rb = wr*32 + mt*16 + qrow;
#pragma unroll
                for (int ntl = 0; ntl < 4; ++ntl){
                    const int cb = wc*32 + ntl*8 + 2*qcol;
                    const float bz0 = pB1[ch*64 + cb], bz1 = pB1[ch*64 + cb + 1];
                    float2 h0, h1;
                    h0.x = __uint_as_float(to_tf32(gelu_exact(acc1[mt][ntl][0] + bz0)));
                    h0.y = __uint_as_float(to_tf32(gelu_exact(acc1[mt][ntl][1] + bz1)));
                    h1.x = __uint_as_float(to_tf32(gelu_exact(acc1[mt][ntl][2] + bz0)));
                    h1.y = __uint_as_float(to_tf32(gelu_exact(acc1[mt][ntl][3] + bz1)));
                    *(float2*)(sHT + rb*SVS + cb)       = h0;
                    *(float2*)(sHT + (rb+8)*SVS + cb)   = h1;
                }
            }
            CP_WAIT0();        // W2[ch] resident (W1 next may still be in flight? no:
                               // wait_group 0 waits all -> slight overlap loss, safe)
            __syncthreads();   // sHT visible to all, sW1 ready

            // ---- GEMM2 accumulate: T += H(128x64) @ W2chunk(64x128) ----
            {
                const int m0 = wr*32 + qrow;
#pragma unroll 2
                for (int ks = 0; ks < 8; ++ks){
                    const int k0 = ks*8 + qcol;
                    uint32_t A[2][4];
#pragma unroll
                    for (int mt = 0; mt < 2; ++mt){
                        const float* hp = sHT + (m0 + 16*mt)*SVS + k0;
                        A[mt][0] = __float_as_uint(hp[0]);
                        A[mt][1] = __float_as_uint(hp[8*SVS]);
                        A[mt][2] = __float_as_uint(hp[4]);
                        A[mt][3] = __float_as_uint(hp[8*SVS + 4]);
                    }
#pragma unroll
                    for (int ntl = 0; ntl < 8; ++ntl){
                        const float2 bf = *(const float2*)
                            (sWf[1] + ((ks*16 + wc*8 + ntl)*32 + lane)*2);
                        uint32_t B[2] = { __float_as_uint(bf.x), __float_as_uint(bf.y) };
                        MMA_TF32(acc2[0][ntl], A[0], B);
                        MMA_TF32(acc2[1][ntl], A[1], B);
                    }
                }
            }
        } // chunks

        __syncthreads();   // all GEMM2 reads of sHT done before T scatter

        // ---- T = V + D2 + b2 -> sHT (full 128x128, fp32) ----
#pragma unroll
        for (int mt = 0; mt < 2; ++mt){
            const int rb = wr*32 + mt*16 + qrow;
#pragma unroll
            for (int ntl = 0; ntl < 8; ++ntl){
                const int cb = wc*64 + ntl*8 + 2*qcol;
                const float b20 = pB2[cb], b21 = pB2[cb + 1];
                float2 v0 = *(const float2*)(sV + rb*SVS + cb);
                float2 v1 = *(const float2*)(sV + (rb+8)*SVS + cb);
                float2 t0, t1;
                t0.x = v0.x + acc2[mt][ntl][0] + b20;
                t0.y = v0.y + acc2[mt][ntl][1] + b21;
                t1.x = v1.x + acc2[mt][ntl][2] + b20;
                t1.y = v1.y + acc2[mt][ntl][3] + b21;
                *(float2*)(sHT + rb*SVS + cb)     = t0;
                *(float2*)(sHT + (rb+8)*SVS + cb) = t1;
            }
        }
        __syncthreads();

        if (mlp == 0){
            // v2 = LN2(T) -> sV ; v3 = LN3(v2 + bo_recv) -> sV
            ln_row((const float4*)(sHT + lrow*SVS), nullptr, par + 512, par + 640,
                   (float4*)(sV + lrow*SVS), lhalf);
            ln_row((const float4*)(sV + lrow*SVS), par + 128, par + 768, par + 896,
                   (float4*)(sV + lrow*SVS), lhalf);
            // loop-top CP_WAIT0 + syncthreads protect sV/sW0 before next GEMM1
        } else {
            // out = LN4(T) -> GMEM
            ln_row((const float4*)(sHT + lrow*SVS), nullptr, par + 1024, par + 1152,
                   (float4*)(out + grow*128), lhalf);
        }
    }
}

extern "C" void kernel_launch(void* const* d_in, const int* in_sizes, int n_in,
                              void* d_out, int out_size)
{
    const float* x       = (const float*)d_in[0];
    // d_in[1]=router (dead), d_in[3]=bo_send (dead)
    const float* bo_time = (const float*)d_in[2];
    const float* bo_recv = (const float*)d_in[4];
    const float* g1 = (const float*)d_in[5],  *be1 = (const float*)d_in[6];
    const float* g2 = (const float*)d_in[7],  *be2 = (const float*)d_in[8];
    const float* g3 = (const float*)d_in[9],  *be3 = (const float*)d_in[10];
    const float* g4 = (const float*)d_in[11], *be4 = (const float*)d_in[12];
    const float* W1a = (const float*)d_in[13], *b1a = (const float*)d_in[14];
    const float* W2a = (const float*)d_in[15], *b2a = (const float*)d_in[16];
    const float* W1b = (const float*)d_in[17], *b1b = (const float*)d_in[18];
    const float* W2b = (const float*)d_in[19], *b2b = (const float*)d_in[20];
    float* out = (float*)d_out;

    int rows   = in_sizes[0] / 128;   // 131072
    int blocks = rows / TILE_R;       // 1024
    size_t shmem = (size_t)SMEM_FLOATS * sizeof(float);   // 210944 B

    prep_kernel<<<512, 256>>>(W1a, W2a, W1b, W2b);

    cudaFuncSetAttribute(tsal_mma_kernel,
                         cudaFuncAttributeMaxDynamicSharedMemorySize, (int)shmem);
    tsal_mma_kernel<<<blocks, THREADS, shmem>>>(
        x, bo_time, bo_recv,
        g1, be1, g2, be2, g3, be3, g4, be4,
        b1a, b2a, b1b, b2b, out);
}

// round 5
// speedup vs baseline: 5.3089x; 1.3710x over previous
#include <cuda_runtime.h>
#include <cstdint>

#define THREADS 512
#define TILE_R  128

// ---- SMEM byte offsets ----
#define OFF_V    0        // fp32 V/T: 128 x 132 x 4 = 67584
#define OFF_VB   67584    // bf16 V:   128 x 68 words = 34816
#define OFF_H    102400   // bf16 H:   128 x 36 words = 18432
#define OFF_W1A  120832   // 16384
#define OFF_W1B  137216   // 16384
#define OFF_W2A  153600   // 16384
#define OFF_W2B  169984   // 16384
#define OFF_PAR  186368   // 2560 floats = 10240
#define SMEM_BYTES 196608

#define VSTR  132   // fp32 words / row (sV)
#define VBSTR 68    // u32 words / row (sVb)  -> row bank offset 4: conflict-free gathers
#define HSTR  36    // u32 words / row (sH)   -> row bank offset 4

// pre-packed bf16 B-fragment weight images: slot ((kt*NT+nt)*32+lane) -> uint2 {b0,b1}
__device__ uint2 g_w1img[2][8][2048];   // GEMM1 B: K=128, N=64 per chunk
__device__ uint2 g_w2img[2][8][2048];   // GEMM2 B: K=64,  N=128 per chunk

__device__ __forceinline__ uint32_t smem_u32(const void* p){
    uint32_t a;
    asm("{ .reg .u64 t; cvta.to.shared.u64 t, %1; cvt.u32.u64 %0, t; }"
        : "=r"(a) : "l"(p));
    return a;
}
__device__ __forceinline__ uint32_t bf2(float lo, float hi){
    uint32_t r;
    asm("cvt.rn.bf16x2.f32 %0, %1, %2;" : "=r"(r) : "f"(hi), "f"(lo));
    return r;
}
__device__ __forceinline__ float gelu_exact(float x){
    return 0.5f * x * (1.0f + erff(x * 0.70710678118654752440f));
}

#define MMA_BF16(d, a, b) asm volatile( \
    "mma.sync.aligned.m16n8k16.row.col.f32.bf16.bf16.f32 " \
    "{%0,%1,%2,%3},{%4,%5,%6,%7},{%8,%9},{%0,%1,%2,%3};" \
    : "+f"((d)[0]), "+f"((d)[1]), "+f"((d)[2]), "+f"((d)[3]) \
    : "r"((a)[0]), "r"((a)[1]), "r"((a)[2]), "r"((a)[3]), \
      "r"((b).x), "r"((b).y))

#define CP_ASYNC16(dst, src) asm volatile( \
    "cp.async.cg.shared.global [%0], [%1], 16;" :: "r"(dst), "l"(src))
#define CP_COMMIT() asm volatile("cp.async.commit_group;" ::: "memory")
#define CP_WAIT(n)  asm volatile("cp.async.wait_group %0;" :: "n"(n) : "memory")

// stage one 16KB weight image (1024 x 16B) with 512 threads, one commit group
__device__ __forceinline__ void stage16k(uint32_t dst, const void* src, int tid){
    const float4* s4 = (const float4*)src;
    CP_ASYNC16(dst + (uint32_t)tid * 16u, s4 + tid);
    CP_ASYNC16(dst + (uint32_t)(tid + 512) * 16u, s4 + tid + 512);
    CP_COMMIT();
}

// ---------------- prep: pack bf16 B-fragment weight images ----------------
__global__ void prep_kernel(const float* __restrict__ W1a, const float* __restrict__ W2a,
                            const float* __restrict__ W1b, const float* __restrict__ W2b)
{
    int idx  = blockIdx.x * 256 + threadIdx.x;   // 0..65535
    int isW2 = idx >> 15;
    int r    = idx & 32767;
    int m    = r >> 14;
    int c    = (r >> 11) & 7;
    int s    = r & 2047;
    int lane = s & 31;
    int tile = s >> 5;                            // 0..63
    if (!isW2){
        int ks = tile >> 3, nt = tile & 7;
        const float* W1 = m ? W1b : W1a;
        int n = c * 64 + nt * 8 + (lane >> 2);
        int k = ks * 16 + (lane & 3) * 2;
        uint2 v;
        v.x = bf2(W1[(size_t)k * 512 + n],       W1[(size_t)(k + 1) * 512 + n]);
        v.y = bf2(W1[(size_t)(k + 8) * 512 + n], W1[(size_t)(k + 9) * 512 + n]);
        g_w1img[m][c][s] = v;
    } else {
        int ks = tile >> 4, nt = tile & 15;
        const float* W2 = m ? W2b : W2a;
        int n = nt * 8 + (lane >> 2);
        int k = c * 64 + ks * 16 + (lane & 3) * 2;
        uint2 v;
        v.x = bf2(W2[(size_t)k * 128 + n],       W2[(size_t)(k + 1) * 128 + n]);
        v.y = bf2(W2[(size_t)(k + 8) * 128 + n], W2[(size_t)(k + 9) * 128 + n]);
        g_w2img[m][c][s] = v;
    }
}

// ---------------- main kernel ----------------
extern "C" __global__ void __launch_bounds__(THREADS, 1)
tsal_bf16_kernel(const float* __restrict__ x,
                 const float* __restrict__ bo_time, const float* __restrict__ bo_recv,
                 const float* __restrict__ g1, const float* __restrict__ be1,
                 const float* __restrict__ g2, const float* __restrict__ be2,
                 const float* __restrict__ g3, const float* __restrict__ be3,
                 const float* __restrict__ g4, const float* __restrict__ be4,
                 const float* __restrict__ b1a, const float* __restrict__ b2a,
                 const float* __restrict__ b1b, const float* __restrict__ b2b,
                 float* __restrict__ out)
{
    extern __shared__ __align__(16) char smb[];
    float*    sV  = (float*)(smb + OFF_V);
    uint32_t* sVb = (uint32_t*)(smb + OFF_VB);
    uint32_t* sH  = (uint32_t*)(smb + OFF_H);
    float*    par = (float*)(smb + OFF_PAR);
    const uint2* w1buf[2] = { (const uint2*)(smb + OFF_W1A), (const uint2*)(smb + OFF_W1B) };
    const uint2* w2buf[2] = { (const uint2*)(smb + OFF_W2A), (const uint2*)(smb + OFF_W2B) };
    const uint32_t w1addr[2] = { smem_u32(smb + OFF_W1A), smem_u32(smb + OFF_W1B) };
    const uint32_t w2addr[2] = { smem_u32(smb + OFF_W2A), smem_u32(smb + OFF_W2B) };

    const int tid  = threadIdx.x;
    const int lane = tid & 31, wid = tid >> 5;
    const int wr   = wid & 3, wc = wid >> 2;      // warp grid: 4 rows x 4 cols
    const int qrow = lane >> 2, qcol = lane & 3;
    const int lrow = tid >> 2, lq = tid & 3;      // LN: 4 threads/row

    // prefetch phase-0 weights immediately (groups 0,1)
    stage16k(w1addr[0], &g_w1img[0][0][0], tid);
    stage16k(w2addr[0], &g_w2img[0][0][0], tid);

    // stage params
    for (int i = tid; i < 128; i += THREADS){
        par[i]        = bo_time[i]; par[128 + i]  = bo_recv[i];
        par[256 + i]  = g1[i];      par[384 + i]  = be1[i];
        par[512 + i]  = g2[i];      par[640 + i]  = be2[i];
        par[768 + i]  = g3[i];      par[896 + i]  = be3[i];
        par[1024 + i] = g4[i];      par[1152 + i] = be4[i];
        par[1280 + i] = b2a[i];     par[1408 + i] = b2b[i];
    }
    for (int i = tid; i < 512; i += THREADS){
        par[1536 + i] = b1a[i];     par[2048 + i] = b1b[i];
    }
    __syncthreads();

    // ---- LN1: v1 = LN(x + bo_time) -> sV (fp32) + sVb (bf16) ----
    const size_t grow = (size_t)blockIdx.x * TILE_R + lrow;
    {
        float4 v[8];
        float s = 0.f, q = 0.f;
#pragma unroll
        for (int i = 0; i < 8; ++i){
            int c = 16 * i + 4 * lq;
            float4 a = *(const float4*)(x + grow * 128 + c);
            a.x += par[c + 0]; a.y += par[c + 1]; a.z += par[c + 2]; a.w += par[c + 3];
            v[i] = a;
            s += a.x + a.y + a.z + a.w;
            q = fmaf(a.x, a.x, q); q = fmaf(a.y, a.y, q);
            q = fmaf(a.z, a.z, q); q = fmaf(a.w, a.w, q);
        }
        s += __shfl_xor_sync(0xffffffffu, s, 1, 4); s += __shfl_xor_sync(0xffffffffu, s, 2, 4);
        q += __shfl_xor_sync(0xffffffffu, q, 1, 4); q += __shfl_xor_sync(0xffffffffu, q, 2, 4);
        float mu = s * 0.0078125f;
        float rs = rsqrtf(q * 0.0078125f - mu * mu + 1e-5f);
#pragma unroll
        for (int i = 0; i < 8; ++i){
            int c = 16 * i + 4 * lq;
            float4 a = v[i], o;
            o.x = (a.x - mu) * rs * par[256 + c + 0] + par[384 + c + 0];
            o.y = (a.y - mu) * rs * par[256 + c + 1] + par[384 + c + 1];
            o.z = (a.z - mu) * rs * par[256 + c + 2] + par[384 + c + 2];
            o.w = (a.w - mu) * rs * par[256 + c + 3] + par[384 + c + 3];
            *(float4*)(sV + lrow * VSTR + c) = o;
            sVb[lrow * VBSTR + (c >> 1)]     = bf2(o.x, o.y);
            sVb[lrow * VBSTR + (c >> 1) + 1] = bf2(o.z, o.w);
        }
    }

    float acc2[2][4][4];
    const uint32_t* a1base = sVb + (wr * 32 + qrow) * VBSTR + qcol;
    const uint32_t* a2base = sH  + (wr * 32 + qrow) * HSTR  + qcol;

    for (int p = 0; p < 16; ++p){
        const int mlp = p >> 3, ch = p & 7, buf = p & 1, nbuf = buf ^ 1;
        const float* pB1 = par + (mlp ? 2048 : 1536) + ch * 64;
        const float* pB2 = par + (mlp ? 1408 : 1280);

        if (ch == 0){
#pragma unroll
            for (int a = 0; a < 2; ++a)
#pragma unroll
                for (int b = 0; b < 4; ++b)
#pragma unroll
                    for (int d = 0; d < 4; ++d) acc2[a][b][d] = 0.f;
        }

        // W1[p] resident (allow next group pending); LN/epilogue writes of prev phase done
        CP_WAIT(1);
        __syncthreads();
        if (p < 15) stage16k(w1addr[nbuf], &g_w1img[(p+1) >> 3][(p+1) & 7][0], tid);

        // ---- GEMM1: H(128x64) = Vb(128x128) @ W1[p] ----
        float acc1[2][2][4];
#pragma unroll
        for (int a = 0; a < 2; ++a)
#pragma unroll
            for (int b = 0; b < 2; ++b)
#pragma unroll
                for (int d = 0; d < 4; ++d) acc1[a][b][d] = 0.f;
        {
            const uint2* bp = w1buf[buf] + (wc * 2) * 32 + lane;
#pragma unroll
            for (int ks = 0; ks < 8; ++ks){
                uint32_t A[2][4];
#pragma unroll
                for (int mt = 0; mt < 2; ++mt){
                    const uint32_t* ap = a1base + mt * 16 * VBSTR + ks * 8;
                    A[mt][0] = ap[0];
                    A[mt][1] = ap[8 * VBSTR];
                    A[mt][2] = ap[4];
                    A[mt][3] = ap[8 * VBSTR + 4];
                }
#pragma unroll
                for (int ntl = 0; ntl < 2; ++ntl){
                    uint2 B = bp[ks * 256 + ntl * 32];
                    MMA_BF16(acc1[0][ntl], A[0], B);
                    MMA_BF16(acc1[1][ntl], A[1], B);
                }
            }
        }

        // W2[p] resident (final phase: wait all)
        if (p < 15) CP_WAIT(1); else CP_WAIT(0);
        __syncthreads();
        if (p < 15) stage16k(w2addr[nbuf], &g_w2img[(p+1) >> 3][(p+1) & 7][0], tid);

        // ---- epilogue: bias + exact GELU -> sH (bf16) ----
#pragma unroll
        for (int mt = 0; mt < 2; ++mt){
            const int rb = wr * 32 + mt * 16 + qrow;
#pragma unroll
            for (int ntl = 0; ntl < 2; ++ntl){
                const int cb = wc * 16 + ntl * 8 + 2 * qcol;
                const float bz0 = pB1[cb], bz1 = pB1[cb + 1];
                sH[rb * HSTR + (cb >> 1)] =
                    bf2(gelu_exact(acc1[mt][ntl][0] + bz0),
                        gelu_exact(acc1[mt][ntl][1] + bz1));
                sH[(rb + 8) * HSTR + (cb >> 1)] =
                    bf2(gelu_exact(acc1[mt][ntl][2] + bz0),
                        gelu_exact(acc1[mt][ntl][3] + bz1));
            }
        }
        __syncthreads();   // sH visible

        // ---- GEMM2 accumulate: T += H(128x64) @ W2[p](64x128) ----
        {
            const uint2* bp = w2buf[buf] + (wc * 4) * 32 + lane;
#pragma unroll
            for (int ks = 0; ks < 4; ++ks){
                uint32_t A[2][4];
#pragma unroll
                for (int mt = 0; mt < 2; ++mt){
                    const uint32_t* ap = a2base + mt * 16 * HSTR + ks * 8;
                    A[mt][0] = ap[0];
                    A[mt][1] = ap[8 * HSTR];
                    A[mt][2] = ap[4];
                    A[mt][3] = ap[8 * HSTR + 4];
                }
#pragma unroll
                for (int ntl = 0; ntl < 4; ++ntl){
                    uint2 B = bp[ks * 512 + ntl * 32];
                    MMA_BF16(acc2[0][ntl], A[0], B);
                    MMA_BF16(acc2[1][ntl], A[1], B);
                }
            }
        }

        if (ch == 7){
            // ---- T = V + D2 + b2, in place in sV (fp32, exact residual) ----
#pragma unroll
            for (int mt = 0; mt < 2; ++mt){
                const int rb = wr * 32 + mt * 16 + qrow;
#pragma unroll
                for (int ntl = 0; ntl < 4; ++ntl){
                    const int cb = wc * 32 + ntl * 8 + 2 * qcol;
                    const float b20 = pB2[cb], b21 = pB2[cb + 1];
                    float2* v0p = (float2*)(sV + rb * VSTR + cb);
                    float2* v1p = (float2*)(sV + (rb + 8) * VSTR + cb);
                    float2 v0 = *v0p, v1 = *v1p;
                    v0.x += acc2[mt][ntl][0] + b20; v0.y += acc2[mt][ntl][1] + b21;
                    v1.x += acc2[mt][ntl][2] + b20; v1.y += acc2[mt][ntl][3] + b21;
                    *v0p = v0; *v1p = v1;
                }
            }
            __syncthreads();

            // ---- LayerNorm chain on T ----
            float4 v[8];
            float s = 0.f, q = 0.f;
#pragma unroll
            for (int i = 0; i < 8; ++i){
                int c = 16 * i + 4 * lq;
                float4 a = *(const float4*)(sV + lrow * VSTR + c);
                v[i] = a;
                s += a.x + a.y + a.z + a.w;
                q = fmaf(a.x, a.x, q); q = fmaf(a.y, a.y, q);
                q = fmaf(a.z, a.z, q); q = fmaf(a.w, a.w, q);
            }
            s += __shfl_xor_sync(0xffffffffu, s, 1, 4); s += __shfl_xor_sync(0xffffffffu, s, 2, 4);
            q += __shfl_xor_sync(0xffffffffu, q, 1, 4); q += __shfl_xor_sync(0xffffffffu, q, 2, 4);
            float mu = s * 0.0078125f;
            float rs = rsqrtf(q * 0.0078125f - mu * mu + 1e-5f);

            if (mlp == 0){
                // v2 = LN2(T); v3 = LN3(v2 + bo_recv) -> sV + sVb
                float s2 = 0.f, q2 = 0.f;
#pragma unroll
                for (int i = 0; i < 8; ++i){
                    int c = 16 * i + 4 * lq;
                    float4 a = v[i], o;
                    o.x = (a.x - mu) * rs * par[512 + c + 0] + par[640 + c + 0] + par[128 + c + 0];
                    o.y = (a.y - mu) * rs * par[512 + c + 1] + par[640 + c + 1] + par[128 + c + 1];
                    o.z = (a.z - mu) * rs * par[512 + c + 2] + par[640 + c + 2] + par[128 + c + 2];
                    o.w = (a.w - mu) * rs * par[512 + c + 3] + par[640 + c + 3] + par[128 + c + 3];
                    v[i] = o;
                    s2 += o.x + o.y + o.z + o.w;
                    q2 = fmaf(o.x, o.x, q2); q2 = fmaf(o.y, o.y, q2);
                    q2 = fmaf(o.z, o.z, q2); q2 = fmaf(o.w, o.w, q2);
                }
                s2 += __shfl_xor_sync(0xffffffffu, s2, 1, 4); s2 += __shfl_xor_sync(0xffffffffu, s2, 2, 4);
                q2 += __shfl_xor_sync(0xffffffffu, q2, 1, 4); q2 += __shfl_xor_sync(0xffffffffu, q2, 2, 4);
                float mu2 = s2 * 0.0078125f;
                float rs2 = rsqrtf(q2 * 0.0078125f - mu2 * mu2 + 1e-5f);
#pragma unroll
                for (int i = 0; i < 8; ++i){
                    int c = 16 * i + 4 * lq;
                    float4 a = v[i], o;
                    o.x = (a.x - mu2) * rs2 * par[768 + c + 0] + par[896 + c + 0];
                    o.y = (a.y - mu2) * rs2 * par[768 + c + 1] + par[896 + c + 1];
                    o.z = (a.z - mu2) * rs2 * par[768 + c + 2] + par[896 + c + 2];
                    o.w = (a.w - mu2) * rs2 * par[768 + c + 3] + par[896 + c + 3];
                    *(float4*)(sV + lrow * VSTR + c) = o;
                    sVb[lrow * VBSTR + (c >> 1)]     = bf2(o.x, o.y);
                    sVb[lrow * VBSTR + (c >> 1) + 1] = bf2(o.z, o.w);
                }
                // next-phase top sync orders these writes before GEMM1 reads
            } else {
                // out = LN4(T) -> GMEM
#pragma unroll
                for (int i = 0; i < 8; ++i){
                    int c = 16 * i + 4 * lq;
                    float4 a = v[i], o;
                    o.x = (a.x - mu) * rs * par[1024 + c + 0] + par[1152 + c + 0];
                    o.y = (a.y - mu) * rs * par[1024 + c + 1] + par[1152 + c + 1];
                    o.z = (a.z - mu) * rs * par[1024 + c + 2] + par[1152 + c + 2];
                    o.w = (a.w - mu) * rs * par[1024 + c + 3] + par[1152 + c + 3];
                    *(float4*)(out + grow * 128 + c) = o;
                }
            }
        }
    }
}

extern "C" void kernel_launch(void* const* d_in, const int* in_sizes, int n_in,
                              void* d_out, int out_size)
{
    const float* x       = (const float*)d_in[0];
    // d_in[1]=router (dead), d_in[3]=bo_send (dead)
    const float* bo_time = (const float*)d_in[2];
    const float* bo_recv = (const float*)d_in[4];
    const float* g1 = (const float*)d_in[5],  *be1 = (const float*)d_in[6];
    const float* g2 = (const float*)d_in[7],  *be2 = (const float*)d_in[8];
    const float* g3 = (const float*)d_in[9],  *be3 = (const float*)d_in[10];
    const float* g4 = (const float*)d_in[11], *be4 = (const float*)d_in[12];
    const float* W1a = (const float*)d_in[13], *b1a = (const float*)d_in[14];
    const float* W2a = (const float*)d_in[15], *b2a = (const float*)d_in[16];
    const float* W1b = (const float*)d_in[17], *b1b = (const float*)d_in[18];
    const float* W2b = (const float*)d_in[19], *b2b = (const float*)d_in[20];
    float* out = (float*)d_out;

    int rows   = in_sizes[0] / 128;   // 131072
    int blocks = rows / TILE_R;       // 1024

    prep_kernel<<<256, 256>>>(W1a, W2a, W1b, W2b);

    cudaFuncSetAttribute(tsal_bf16_kernel,
                         cudaFuncAttributeMaxDynamicSharedMemorySize, SMEM_BYTES);
    tsal_bf16_kernel<<<blocks, THREADS, SMEM_BYTES>>>(
        x, bo_time, bo_recv,
        g1, be1, g2, be2, g3, be3, g4, be4,
        b1a, b2a, b1b, b2b, out);
}

// round 6
// speedup vs baseline: 5.4138x; 1.0198x over previous
#include <cuda_runtime.h>
#include <cstdint>

#define THREADS 512
#define TILE_R  128

// ---- SMEM byte offsets ----
#define OFF_V    0        // fp32 V/T: 128 x 132 x 4 = 67584
#define OFF_VB   67584    // bf16 V:   128 x 68 u32  = 34816
#define OFF_H0   102400   // bf16 H buf0: 128 x 36 u32 = 18432
#define OFF_H1   120832   // bf16 H buf1
#define OFF_W1A  139264   // 16384
#define OFF_W1B  155648   // 16384
#define OFF_W2A  172032   // 16384
#define OFF_W2B  188416   // 16384
#define OFF_PAR  204800   // 2560 floats
#define SMEM_BYTES 215040

#define VSTR  132
#define VBSTR 68
#define HSTR  36

// pre-packed bf16 B-fragment weight images
__device__ uint2 g_w1img[2][8][2048];   // GEMM1 B: K=128, N=64 per chunk
__device__ uint2 g_w2img[2][8][2048];   // GEMM2 B: K=64,  N=128 per chunk

__device__ __forceinline__ uint32_t smem_u32(const void* p){
    uint32_t a;
    asm("{ .reg .u64 t; cvta.to.shared.u64 t, %1; cvt.u32.u64 %0, t; }"
        : "=r"(a) : "l"(p));
    return a;
}
__device__ __forceinline__ uint32_t bf2(float lo, float hi){
    uint32_t r;
    asm("cvt.rn.bf16x2.f32 %0, %1, %2;" : "=r"(r) : "f"(hi), "f"(lo));
    return r;
}
__device__ __forceinline__ float gelu_exact(float x){
    return 0.5f * x * (1.0f + erff(x * 0.70710678118654752440f));
}

#define MMA_BF16(d, a, b) asm volatile( \
    "mma.sync.aligned.m16n8k16.row.col.f32.bf16.bf16.f32 " \
    "{%0,%1,%2,%3},{%4,%5,%6,%7},{%8,%9},{%0,%1,%2,%3};" \
    : "+f"((d)[0]), "+f"((d)[1]), "+f"((d)[2]), "+f"((d)[3]) \
    : "r"((a)[0]), "r"((a)[1]), "r"((a)[2]), "r"((a)[3]), \
      "r"((b).x), "r"((b).y))

#define CP_ASYNC16(dst, src) asm volatile( \
    "cp.async.cg.shared.global [%0], [%1], 16;" :: "r"(dst), "l"(src))
#define CP_COMMIT() asm volatile("cp.async.commit_group;" ::: "memory")
#define CP_WAIT(n)  asm volatile("cp.async.wait_group %0;" :: "n"(n) : "memory")

__device__ __forceinline__ void stage16k(uint32_t dst, const void* src, int tid){
    const float4* s4 = (const float4*)src;
    CP_ASYNC16(dst + (uint32_t)tid * 16u, s4 + tid);
    CP_ASYNC16(dst + (uint32_t)(tid + 512) * 16u, s4 + tid + 512);
    CP_COMMIT();
}

// ---- GEMM1: acc1 += Vb(128x128) @ W1chunk(128x64), warp tile 32x16 ----
__device__ __forceinline__ void gemm1(float acc1[2][2][4],
                                      const uint32_t* __restrict__ a1base,
                                      const uint2* __restrict__ w1,
                                      int wc, int lane){
#pragma unroll
    for (int a = 0; a < 2; ++a)
#pragma unroll
        for (int b = 0; b < 2; ++b)
#pragma unroll
            for (int d = 0; d < 4; ++d) acc1[a][b][d] = 0.f;
    const uint2* bp = w1 + (wc * 2) * 32 + lane;
#pragma unroll
    for (int ks = 0; ks < 8; ++ks){
        uint32_t A[2][4];
#pragma unroll
        for (int mt = 0; mt < 2; ++mt){
            const uint32_t* ap = a1base + mt * 16 * VBSTR + ks * 8;
            A[mt][0] = ap[0];
            A[mt][1] = ap[8 * VBSTR];
            A[mt][2] = ap[4];
            A[mt][3] = ap[8 * VBSTR + 4];
        }
#pragma unroll
        for (int ntl = 0; ntl < 2; ++ntl){
            uint2 B = bp[ks * 256 + ntl * 32];
            MMA_BF16(acc1[0][ntl], A[0], B);
            MMA_BF16(acc1[1][ntl], A[1], B);
        }
    }
}

// ---- GEMM2: acc2 += H(128x64) @ W2chunk(64x128), warp tile 32x32 ----
__device__ __forceinline__ void gemm2(float acc2[2][4][4],
                                      const uint32_t* __restrict__ sHb,
                                      const uint2* __restrict__ w2,
                                      int wr, int wc, int lane, int qrow, int qcol){
    const uint32_t* a2base = sHb + (wr * 32 + qrow) * HSTR + qcol;
    const uint2* bp = w2 + (wc * 4) * 32 + lane;
#pragma unroll
    for (int ks = 0; ks < 4; ++ks){
        uint32_t A[2][4];
#pragma unroll
        for (int mt = 0; mt < 2; ++mt){
            const uint32_t* ap = a2base + mt * 16 * HSTR + ks * 8;
            A[mt][0] = ap[0];
            A[mt][1] = ap[8 * HSTR];
            A[mt][2] = ap[4];
            A[mt][3] = ap[8 * HSTR + 4];
        }
#pragma unroll
        for (int ntl = 0; ntl < 4; ++ntl){
            uint2 B = bp[ks * 512 + ntl * 32];
            MMA_BF16(acc2[0][ntl], A[0], B);
            MMA_BF16(acc2[1][ntl], A[1], B);
        }
    }
}

// ---- epilogue: bias + exact GELU -> sH buffer (bf16) ----
__device__ __forceinline__ void epi1(const float acc1[2][2][4],
                                     uint32_t* __restrict__ sHb,
                                     const float* __restrict__ pB1,
                                     int wr, int wc, int qrow, int qcol){
#pragma unroll
    for (int mt = 0; mt < 2; ++mt){
        const int rb = wr * 32 + mt * 16 + qrow;
#pragma unroll
        for (int ntl = 0; ntl < 2; ++ntl){
            const int cb = wc * 16 + ntl * 8 + 2 * qcol;
            const float bz0 = pB1[cb], bz1 = pB1[cb + 1];
            sHb[rb * HSTR + (cb >> 1)] =
                bf2(gelu_exact(acc1[mt][ntl][0] + bz0),
                    gelu_exact(acc1[mt][ntl][1] + bz1));
            sHb[(rb + 8) * HSTR + (cb >> 1)] =
                bf2(gelu_exact(acc1[mt][ntl][2] + bz0),
                    gelu_exact(acc1[mt][ntl][3] + bz1));
        }
    }
}

// ---------------- prep: pack bf16 B-fragment weight images ----------------
__global__ void prep_kernel(const float* __restrict__ W1a, const float* __restrict__ W2a,
                            const float* __restrict__ W1b, const float* __restrict__ W2b)
{
    int idx  = blockIdx.x * 256 + threadIdx.x;
    int isW2 = idx >> 15;
    int r    = idx & 32767;
    int m    = r >> 14;
    int c    = (r >> 11) & 7;
    int s    = r & 2047;
    int lane = s & 31;
    int tile = s >> 5;
    if (!isW2){
        int ks = tile >> 3, nt = tile & 7;
        const float* W1 = m ? W1b : W1a;
        int n = c * 64 + nt * 8 + (lane >> 2);
        int k = ks * 16 + (lane & 3) * 2;
        uint2 v;
        v.x = bf2(W1[(size_t)k * 512 + n],       W1[(size_t)(k + 1) * 512 + n]);
        v.y = bf2(W1[(size_t)(k + 8) * 512 + n], W1[(size_t)(k + 9) * 512 + n]);
        g_w1img[m][c][s] = v;
    } else {
        int ks = tile >> 4, nt = tile & 15;
        const float* W2 = m ? W2b : W2a;
        int n = nt * 8 + (lane >> 2);
        int k = c * 64 + ks * 16 + (lane & 3) * 2;
        uint2 v;
        v.x = bf2(W2[(size_t)k * 128 + n],       W2[(size_t)(k + 1) * 128 + n]);
        v.y = bf2(W2[(size_t)(k + 8) * 128 + n], W2[(size_t)(k + 9) * 128 + n]);
        g_w2img[m][c][s] = v;
    }
}

// ---------------- main kernel ----------------
extern "C" __global__ void __launch_bounds__(THREADS, 1)
tsal_pipe_kernel(const float* __restrict__ x,
                 const float* __restrict__ bo_time, const float* __restrict__ bo_recv,
                 const float* __restrict__ g1, const float* __restrict__ be1,
                 const float* __restrict__ g2, const float* __restrict__ be2,
                 const float* __restrict__ g3, const float* __restrict__ be3,
                 const float* __restrict__ g4, const float* __restrict__ be4,
                 const float* __restrict__ b1a, const float* __restrict__ b2a,
                 const float* __restrict__ b1b, const float* __restrict__ b2b,
                 float* __restrict__ out)
{
    extern __shared__ __align__(16) char smb[];
    float*    sV  = (float*)(smb + OFF_V);
    uint32_t* sVb = (uint32_t*)(smb + OFF_VB);
    float*    par = (float*)(smb + OFF_PAR);
    uint32_t* sHbuf[2] = { (uint32_t*)(smb + OFF_H0), (uint32_t*)(smb + OFF_H1) };
    const uint2* w1buf[2] = { (const uint2*)(smb + OFF_W1A), (const uint2*)(smb + OFF_W1B) };
    const uint2* w2buf[2] = { (const uint2*)(smb + OFF_W2A), (const uint2*)(smb + OFF_W2B) };
    const uint32_t w1addr[2] = { smem_u32(smb + OFF_W1A), smem_u32(smb + OFF_W1B) };
    const uint32_t w2addr[2] = { smem_u32(smb + OFF_W2A), smem_u32(smb + OFF_W2B) };

    const int tid  = threadIdx.x;
    const int lane = tid & 31, wid = tid >> 5;
    const int wr   = wid & 3, wc = wid >> 2;
    const int qrow = lane >> 2, qcol = lane & 3;
    const int lrow = tid >> 2, lq = tid & 3;

    // prefetch W1[0], W2[0], W1[1]  (groups G0, G1, G2)
    stage16k(w1addr[0], &g_w1img[0][0][0], tid);
    stage16k(w2addr[0], &g_w2img[0][0][0], tid);
    stage16k(w1addr[1], &g_w1img[0][1][0], tid);

    // stage params
    for (int i = tid; i < 128; i += THREADS){
        par[i]        = bo_time[i]; par[128 + i]  = bo_recv[i];
        par[256 + i]  = g1[i];      par[384 + i]  = be1[i];
        par[512 + i]  = g2[i];      par[640 + i]  = be2[i];
        par[768 + i]  = g3[i];      par[896 + i]  = be3[i];
        par[1024 + i] = g4[i];      par[1152 + i] = be4[i];
        par[1280 + i] = b2a[i];     par[1408 + i] = b2b[i];
    }
    for (int i = tid; i < 512; i += THREADS){
        par[1536 + i] = b1a[i];     par[2048 + i] = b1b[i];
    }
    __syncthreads();

    // ---- LN1: v1 = LN(x + bo_time) -> sV (fp32) + sVb (bf16) ----
    const size_t grow = (size_t)blockIdx.x * TILE_R + lrow;
    {
        float4 v[8];
        float s = 0.f, q = 0.f;
#pragma unroll
        for (int i = 0; i < 8; ++i){
            int c = 16 * i + 4 * lq;
            float4 a = *(const float4*)(x + grow * 128 + c);
            a.x += par[c + 0]; a.y += par[c + 1]; a.z += par[c + 2]; a.w += par[c + 3];
            v[i] = a;
            s += a.x + a.y + a.z + a.w;
            q = fmaf(a.x, a.x, q); q = fmaf(a.y, a.y, q);
            q = fmaf(a.z, a.z, q); q = fmaf(a.w, a.w, q);
        }
        s += __shfl_xor_sync(0xffffffffu, s, 1, 4); s += __shfl_xor_sync(0xffffffffu, s, 2, 4);
        q += __shfl_xor_sync(0xffffffffu, q, 1, 4); q += __shfl_xor_sync(0xffffffffu, q, 2, 4);
        float mu = s * 0.0078125f;
        float rs = rsqrtf(q * 0.0078125f - mu * mu + 1e-5f);
#pragma unroll
        for (int i = 0; i < 8; ++i){
            int c = 16 * i + 4 * lq;
            float4 a = v[i], o;
            o.x = (a.x - mu) * rs * par[256 + c + 0] + par[384 + c + 0];
            o.y = (a.y - mu) * rs * par[256 + c + 1] + par[384 + c + 1];
            o.z = (a.z - mu) * rs * par[256 + c + 2] + par[384 + c + 2];
            o.w = (a.w - mu) * rs * par[256 + c + 3] + par[384 + c + 3];
            *(float4*)(sV + lrow * VSTR + c) = o;
            sVb[lrow * VBSTR + (c >> 1)]     = bf2(o.x, o.y);
            sVb[lrow * VBSTR + (c >> 1) + 1] = bf2(o.z, o.w);
        }
    }

    const uint32_t* a1base = sVb + (wr * 32 + qrow) * VBSTR + qcol;
    float acc2[2][4][4];
#pragma unroll
    for (int a = 0; a < 2; ++a)
#pragma unroll
        for (int b = 0; b < 4; ++b)
#pragma unroll
            for (int d = 0; d < 4; ++d) acc2[a][b][d] = 0.f;

    // ---- preamble: GEMM1[0] + epilogue -> sH[0] ----
    CP_WAIT(2);          // W1[0] resident
    __syncthreads();     // sVb visible
    {
        float acc1[2][2][4];
        gemm1(acc1, a1base, w1buf[0], wc, lane);
        epi1(acc1, sHbuf[0], par + 1536, wr, wc, qrow, qcol);
    }

    // ---- 16 phases: phase p runs GEMM1[p+1] + GEMM2[p], 1 sync/phase ----
    for (int p = 0; p < 16; ++p){
        __syncthreads();   // sH[(p)&1] writes visible; frees buffers for prefetch
        if (p <= 14) stage16k(w2addr[(p + 1) & 1], &g_w2img[(p + 1) >> 3][(p + 1) & 7][0], tid);
        if (p <= 13) stage16k(w1addr[p & 1],       &g_w1img[(p + 2) >> 3][(p + 2) & 7][0], tid);
        if (p <= 13)      CP_WAIT(2);
        else if (p == 14) CP_WAIT(1);
        else              CP_WAIT(0);

        const int ch = p & 7;
        if (ch != 7){
            const int q = p + 1;
            float acc1[2][2][4];
            gemm1(acc1, a1base, w1buf[q & 1], wc, lane);
            gemm2(acc2, sHbuf[p & 1], w2buf[p & 1], wr, wc, lane, qrow, qcol);
            epi1(acc1, sHbuf[q & 1],
                 par + ((q >= 8) ? 2048 : 1536) + (q & 7) * 64, wr, wc, qrow, qcol);
        } else {
            // boundary: finish this MLP, run LN chain, then start next MLP's GEMM1
            gemm2(acc2, sHbuf[1], w2buf[1], wr, wc, lane, qrow, qcol);
            const float* pB2 = par + ((p >= 8) ? 1408 : 1280);
            // T = V + D2 + b2, in place in sV
#pragma unroll
            for (int mt = 0; mt < 2; ++mt){
                const int rb = wr * 32 + mt * 16 + qrow;
#pragma unroll
                for (int ntl = 0; ntl < 4; ++ntl){
                    const int cb = wc * 32 + ntl * 8 + 2 * qcol;
                    const float b20 = pB2[cb], b21 = pB2[cb + 1];
                    float2* v0p = (float2*)(sV + rb * VSTR + cb);
                    float2* v1p = (float2*)(sV + (rb + 8) * VSTR + cb);
                    float2 v0 = *v0p, v1 = *v1p;
                    v0.x += acc2[mt][ntl][0] + b20; v0.y += acc2[mt][ntl][1] + b21;
                    v1.x += acc2[mt][ntl][2] + b20; v1.y += acc2[mt][ntl][3] + b21;
                    *v0p = v0; *v1p = v1;
                }
            }
            __syncthreads();

            // LN on T rows
            float4 v[8];
            float s = 0.f, q = 0.f;
#pragma unroll
            for (int i = 0; i < 8; ++i){
                int c = 16 * i + 4 * lq;
                float4 a = *(const float4*)(sV + lrow * VSTR + c);
                v[i] = a;
                s += a.x + a.y + a.z + a.w;
                q = fmaf(a.x, a.x, q); q = fmaf(a.y, a.y, q);
                q = fmaf(a.z, a.z, q); q = fmaf(a.w, a.w, q);
            }
            s += __shfl_xor_sync(0xffffffffu, s, 1, 4); s += __shfl_xor_sync(0xffffffffu, s, 2, 4);
            q += __shfl_xor_sync(0xffffffffu, q, 1, 4); q += __shfl_xor_sync(0xffffffffu, q, 2, 4);
            float mu = s * 0.0078125f;
            float rs = rsqrtf(q * 0.0078125f - mu * mu + 1e-5f);

            if (p == 7){
                // v2 = LN2(T); v3 = LN3(v2 + bo_recv) -> sV + sVb
                float s2 = 0.f, q2 = 0.f;
#pragma unroll
                for (int i = 0; i < 8; ++i){
                    int c = 16 * i + 4 * lq;
                    float4 a = v[i], o;
                    o.x = (a.x - mu) * rs * par[512 + c + 0] + par[640 + c + 0] + par[128 + c + 0];
                    o.y = (a.y - mu) * rs * par[512 + c + 1] + par[640 + c + 1] + par[128 + c + 1];
                    o.z = (a.z - mu) * rs * par[512 + c + 2] + par[640 + c + 2] + par[128 + c + 2];
                    o.w = (a.w - mu) * rs * par[512 + c + 3] + par[640 + c + 3] + par[128 + c + 3];
                    v[i] = o;
                    s2 += o.x + o.y + o.z + o.w;
                    q2 = fmaf(o.x, o.x, q2); q2 = fmaf(o.y, o.y, q2);
                    q2 = fmaf(o.z, o.z, q2); q2 = fmaf(o.w, o.w, q2);
                }
                s2 += __shfl_xor_sync(0xffffffffu, s2, 1, 4); s2 += __shfl_xor_sync(0xffffffffu, s2, 2, 4);
                q2 += __shfl_xor_sync(0xffffffffu, q2, 1, 4); q2 += __shfl_xor_sync(0xffffffffu, q2, 2, 4);
                float mu2 = s2 * 0.0078125f;
                float rs2 = rsqrtf(q2 * 0.0078125f - mu2 * mu2 + 1e-5f);
#pragma unroll
                for (int i = 0; i < 8; ++i){
                    int c = 16 * i + 4 * lq;
                    float4 a = v[i], o;
                    o.x = (a.x - mu2) * rs2 * par[768 + c + 0] + par[896 + c + 0];
                    o.y = (a.y - mu2) * rs2 * par[768 + c + 1] + par[896 + c + 1];
                    o.z = (a.z - mu2) * rs2 * par[768 + c + 2] + par[896 + c + 2];
                    o.w = (a.w - mu2) * rs2 * par[768 + c + 3] + par[896 + c + 3];
                    *(float4*)(sV + lrow * VSTR + c) = o;
                    sVb[lrow * VBSTR + (c >> 1)]     = bf2(o.x, o.y);
                    sVb[lrow * VBSTR + (c >> 1) + 1] = bf2(o.z, o.w);
                }
                __syncthreads();   // sVb ready for mlp1's GEMM1

                // reset acc2 and run GEMM1[8] + epilogue -> sH[0]
#pragma unroll
                for (int a = 0; a < 2; ++a)
#pragma unroll
                    for (int b = 0; b < 4; ++b)
#pragma unroll
                        for (int d = 0; d < 4; ++d) acc2[a][b][d] = 0.f;
                float acc1[2][2][4];
                gemm1(acc1, a1base, w1buf[0], wc, lane);
                epi1(acc1, sHbuf[0], par + 2048, wr, wc, qrow, qcol);
            } else {
                // p == 15: out = LN4(T) -> GMEM
#pragma unroll
                for (int i = 0; i < 8; ++i){
                    int c = 16 * i + 4 * lq;
                    float4 a = v[i], o;
                    o.x = (a.x - mu) * rs * par[1024 + c + 0] + par[1152 + c + 0];
                    o.y = (a.y - mu) * rs * par[1024 + c + 1] + par[1152 + c + 1];
                    o.z = (a.z - mu) * rs * par[1024 + c + 2] + par[1152 + c + 2];
                    o.w = (a.w - mu) * rs * par[1024 + c + 3] + par[1152 + c + 3];
                    *(float4*)(out + grow * 128 + c) = o;
                }
            }
        }
    }
}

extern "C" void kernel_launch(void* const* d_in, const int* in_sizes, int n_in,
                              void* d_out, int out_size)
{
    const float* x       = (const float*)d_in[0];
    // d_in[1]=router (dead), d_in[3]=bo_send (dead)
    const float* bo_time = (const float*)d_in[2];
    const float* bo_recv = (const float*)d_in[4];
    const float* g1 = (const float*)d_in[5],  *be1 = (const float*)d_in[6];
    const float* g2 = (const float*)d_in[7],  *be2 = (const float*)d_in[8];
    const float* g3 = (const float*)d_in[9],  *be3 = (const float*)d_in[10];
    const float* g4 = (const float*)d_in[11], *be4 = (const float*)d_in[12];
    const float* W1a = (const float*)d_in[13], *b1a = (const float*)d_in[14];
    const float* W2a = (const float*)d_in[15], *b2a = (const float*)d_in[16];
    const float* W1b = (const float*)d_in[17], *b1b = (const float*)d_in[18];
    const float* W2b = (const float*)d_in[19], *b2b = (const float*)d_in[20];
    float* out = (float*)d_out;

    int rows   = in_sizes[0] / 128;   // 131072
    int blocks = rows / TILE_R;       // 1024

    prep_kernel<<<256, 256>>>(W1a, W2a, W1b, W2b);

    cudaFuncSetAttribute(tsal_pipe_kernel,
                         cudaFuncAttributeMaxDynamicSharedMemorySize, SMEM_BYTES);
    tsal_pipe_kernel<<<blocks, THREADS, SMEM_BYTES>>>(
        x, bo_time, bo_recv,
        g1, be1, g2, be2, g3, be3, g4, be4,
        b1a, b2a, b1b, b2b, out);
}

// round 7
// speedup vs baseline: 6.4346x; 1.1886x over previous
#include <cuda_runtime.h>
#include <cstdint>

#define THREADS 512
#define TILE_R  128

// ---- SMEM byte offsets ----
#define OFF_V    0        // fp32 V/T: 128 x 132 x 4 = 67584
#define OFF_VB   67584    // bf16 V:   128 x 68 u32  = 34816
#define OFF_H0   102400   // bf16 H buf0: 128 x 36 u32 = 18432
#define OFF_H1   120832   // bf16 H buf1
#define OFF_W1A  139264   // 16384
#define OFF_W1B  155648   // 16384
#define OFF_W2A  172032   // 16384
#define OFF_W2B  188416   // 16384
#define OFF_PAR  204800   // 2560 floats
#define SMEM_BYTES 215040

#define VSTR  132
#define VBSTR 68
#define HSTR  36

// pre-packed bf16 B-fragment weight images
__device__ uint2 g_w1img[2][8][2048];   // GEMM1 B: K=128, N=64 per chunk
__device__ uint2 g_w2img[2][8][2048];   // GEMM2 B: K=64,  N=128 per chunk

__device__ __forceinline__ uint32_t smem_u32(const void* p){
    uint32_t a;
    asm("{ .reg .u64 t; cvta.to.shared.u64 t, %1; cvt.u32.u64 %0, t; }"
        : "=r"(a) : "l"(p));
    return a;
}
__device__ __forceinline__ uint32_t bf2(float lo, float hi){
    uint32_t r;
    asm("cvt.rn.bf16x2.f32 %0, %1, %2;" : "=r"(r) : "f"(hi), "f"(lo));
    return r;
}
// fast GELU (tanh form): x * (1 - 1/(1 + 2^(2.3021293x + 0.10293971x^3)))
__device__ __forceinline__ float gelu_fast(float x){
    float t = x * x;
    float s = fmaf(t, 0.10293971f, 2.3021293f);
    float z = x * s;
    float e;
    asm("ex2.approx.f32 %0, %1;" : "=f"(e) : "f"(z));
    float rc;
    asm("rcp.approx.f32 %0, %1;" : "=f"(rc) : "f"(1.0f + e));
    return x - x * rc;
}

#define MMA_BF16(d, a, b) asm volatile( \
    "mma.sync.aligned.m16n8k16.row.col.f32.bf16.bf16.f32 " \
    "{%0,%1,%2,%3},{%4,%5,%6,%7},{%8,%9},{%0,%1,%2,%3};" \
    : "+f"((d)[0]), "+f"((d)[1]), "+f"((d)[2]), "+f"((d)[3]) \
    : "r"((a)[0]), "r"((a)[1]), "r"((a)[2]), "r"((a)[3]), \
      "r"((b).x), "r"((b).y))

#define LDSM4(r, addr) asm volatile( \
    "ldmatrix.sync.aligned.m8n8.x4.shared.b16 {%0,%1,%2,%3}, [%4];" \
    : "=r"((r)[0]), "=r"((r)[1]), "=r"((r)[2]), "=r"((r)[3]) : "r"(addr))

#define CP_ASYNC16(dst, src) asm volatile( \
    "cp.async.cg.shared.global [%0], [%1], 16;" :: "r"(dst), "l"(src))
#define CP_COMMIT() asm volatile("cp.async.commit_group;" ::: "memory")
#define CP_WAIT(n)  asm volatile("cp.async.wait_group %0;" :: "n"(n) : "memory")

__device__ __forceinline__ void stage16k(uint32_t dst, const void* src, int tid){
    const float4* s4 = (const float4*)src;
    CP_ASYNC16(dst + (uint32_t)tid * 16u, s4 + tid);
    CP_ASYNC16(dst + (uint32_t)(tid + 512) * 16u, s4 + tid + 512);
    CP_COMMIT();
}

// ---- fused GEMM1 (+ optional GEMM2), ldmatrix A-fragments ----
// GEMM1: acc1 = Vb(128x128) @ W1chunk(128x64), warp tile 32x16 (8 k-steps)
// GEMM2: acc2 += H(128x64) @ W2chunk(64x128), warp tile 32x32 (4 k-steps)
__device__ __forceinline__ void gemm12(float acc1[2][2][4], float acc2[2][4][4],
                                       const uint32_t a1ad[2], const uint32_t a2ad[2],
                                       const uint2* __restrict__ w1,
                                       const uint2* __restrict__ w2,
                                       int wc, int lane, bool doG2){
#pragma unroll
    for (int a = 0; a < 2; ++a)
#pragma unroll
        for (int b = 0; b < 2; ++b)
#pragma unroll
            for (int d = 0; d < 4; ++d) acc1[a][b][d] = 0.f;
    const uint2* bp1 = w1 + (wc * 2) * 32 + lane;
    const uint2* bp2 = w2 + (wc * 4) * 32 + lane;
#pragma unroll
    for (int s = 0; s < 4; ++s){
#pragma unroll
        for (int kk = 0; kk < 2; ++kk){
            const int ks = 2 * s + kk;
            uint32_t A0[4], A1[4];
            LDSM4(A0, a1ad[0] + ks * 32u);
            LDSM4(A1, a1ad[1] + ks * 32u);
            uint2 B0 = bp1[ks * 256], B1 = bp1[ks * 256 + 32];
            MMA_BF16(acc1[0][0], A0, B0); MMA_BF16(acc1[0][1], A0, B1);
            MMA_BF16(acc1[1][0], A1, B0); MMA_BF16(acc1[1][1], A1, B1);
        }
        if (doG2){
            uint32_t A0[4], A1[4];
            LDSM4(A0, a2ad[0] + s * 32u);
            LDSM4(A1, a2ad[1] + s * 32u);
#pragma unroll
            for (int ntl = 0; ntl < 4; ++ntl){
                uint2 B = bp2[s * 512 + ntl * 32];
                MMA_BF16(acc2[0][ntl], A0, B);
                MMA_BF16(acc2[1][ntl], A1, B);
            }
        }
    }
}

__device__ __forceinline__ void gemm2_only(float acc2[2][4][4],
                                           const uint32_t a2ad[2],
                                           const uint2* __restrict__ w2,
                                           int wc, int lane){
    const uint2* bp2 = w2 + (wc * 4) * 32 + lane;
#pragma unroll
    for (int s = 0; s < 4; ++s){
        uint32_t A0[4], A1[4];
        LDSM4(A0, a2ad[0] + s * 32u);
        LDSM4(A1, a2ad[1] + s * 32u);
#pragma unroll
        for (int ntl = 0; ntl < 4; ++ntl){
            uint2 B = bp2[s * 512 + ntl * 32];
            MMA_BF16(acc2[0][ntl], A0, B);
            MMA_BF16(acc2[1][ntl], A1, B);
        }
    }
}

// ---- epilogue: bias + fast GELU -> sH buffer (bf16) ----
__device__ __forceinline__ void epi1(const float acc1[2][2][4],
                                     uint32_t* __restrict__ sHb,
                                     const float* __restrict__ pB1,
                                     int wr, int wc, int qrow, int qcol){
#pragma unroll
    for (int mt = 0; mt < 2; ++mt){
        const int rb = wr * 32 + mt * 16 + qrow;
#pragma unroll
        for (int ntl = 0; ntl < 2; ++ntl){
            const int cb = wc * 16 + ntl * 8 + 2 * qcol;
            const float bz0 = pB1[cb], bz1 = pB1[cb + 1];
            sHb[rb * HSTR + (cb >> 1)] =
                bf2(gelu_fast(acc1[mt][ntl][0] + bz0),
                    gelu_fast(acc1[mt][ntl][1] + bz1));
            sHb[(rb + 8) * HSTR + (cb >> 1)] =
                bf2(gelu_fast(acc1[mt][ntl][2] + bz0),
                    gelu_fast(acc1[mt][ntl][3] + bz1));
        }
    }
}

// ---------------- prep: pack bf16 B-fragment weight images ----------------
__global__ void prep_kernel(const float* __restrict__ W1a, const float* __restrict__ W2a,
                            const float* __restrict__ W1b, const float* __restrict__ W2b)
{
    int idx  = blockIdx.x * 256 + threadIdx.x;
    int isW2 = idx >> 15;
    int r    = idx & 32767;
    int m    = r >> 14;
    int c    = (r >> 11) & 7;
    int s    = r & 2047;
    int lane = s & 31;
    int tile = s >> 5;
    if (!isW2){
        int ks = tile >> 3, nt = tile & 7;
        const float* W1 = m ? W1b : W1a;
        int n = c * 64 + nt * 8 + (lane >> 2);
        int k = ks * 16 + (lane & 3) * 2;
        uint2 v;
        v.x = bf2(W1[(size_t)k * 512 + n],       W1[(size_t)(k + 1) * 512 + n]);
        v.y = bf2(W1[(size_t)(k + 8) * 512 + n], W1[(size_t)(k + 9) * 512 + n]);
        g_w1img[m][c][s] = v;
    } else {
        int ks = tile >> 4, nt = tile & 15;
        const float* W2 = m ? W2b : W2a;
        int n = nt * 8 + (lane >> 2);
        int k = c * 64 + ks * 16 + (lane & 3) * 2;
        uint2 v;
        v.x = bf2(W2[(size_t)k * 128 + n],       W2[(size_t)(k + 1) * 128 + n]);
        v.y = bf2(W2[(size_t)(k + 8) * 128 + n], W2[(size_t)(k + 9) * 128 + n]);
        g_w2img[m][c][s] = v;
    }
}

// ---------------- main kernel ----------------
extern "C" __global__ void __launch_bounds__(THREADS, 1)
tsal_ldsm_kernel(const float* __restrict__ x,
                 const float* __restrict__ bo_time, const float* __restrict__ bo_recv,
                 const float* __restrict__ g1, const float* __restrict__ be1,
                 const float* __restrict__ g2, const float* __restrict__ be2,
                 const float* __restrict__ g3, const float* __restrict__ be3,
                 const float* __restrict__ g4, const float* __restrict__ be4,
                 const float* __restrict__ b1a, const float* __restrict__ b2a,
                 const float* __restrict__ b1b, const float* __restrict__ b2b,
                 float* __restrict__ out)
{
    extern __shared__ __align__(16) char smb[];
    float*    sV  = (float*)(smb + OFF_V);
    uint32_t* sVb = (uint32_t*)(smb + OFF_VB);
    float*    par = (float*)(smb + OFF_PAR);
    uint32_t* sHbuf[2] = { (uint32_t*)(smb + OFF_H0), (uint32_t*)(smb + OFF_H1) };
    const uint2* w1buf[2] = { (const uint2*)(smb + OFF_W1A), (const uint2*)(smb + OFF_W1B) };
    const uint2* w2buf[2] = { (const uint2*)(smb + OFF_W2A), (const uint2*)(smb + OFF_W2B) };
    const uint32_t w1addr[2] = { smem_u32(smb + OFF_W1A), smem_u32(smb + OFF_W1B) };
    const uint32_t w2addr[2] = { smem_u32(smb + OFF_W2A), smem_u32(smb + OFF_W2B) };

    const int tid  = threadIdx.x;
    const int lane = tid & 31, wid = tid >> 5;
    const int wr   = wid & 3, wc = wid >> 2;
    const int qrow = lane >> 2, qcol = lane & 3;
    const int lrow = tid >> 2, lq = tid & 3;

    // ldmatrix per-lane source coordinates
    const int lmRow = ((lane >> 3) & 1) * 8 + (lane & 7);
    const int lmCol = (lane >> 4) * 4;      // u32 offset
    uint32_t a1ad[2], a2ad[2][2];
    {
        const uint32_t vbA = smem_u32(sVb);
#pragma unroll
        for (int mt = 0; mt < 2; ++mt){
            int row = wr * 32 + mt * 16 + lmRow;
            a1ad[mt] = vbA + (uint32_t)(row * VBSTR + lmCol) * 4u;
            a2ad[0][mt] = smem_u32(sHbuf[0]) + (uint32_t)(row * HSTR + lmCol) * 4u;
            a2ad[1][mt] = smem_u32(sHbuf[1]) + (uint32_t)(row * HSTR + lmCol) * 4u;
        }
    }

    // prefetch W1[0], W2[0], W1[1]
    stage16k(w1addr[0], &g_w1img[0][0][0], tid);
    stage16k(w2addr[0], &g_w2img[0][0][0], tid);
    stage16k(w1addr[1], &g_w1img[0][1][0], tid);

    // stage params
    for (int i = tid; i < 128; i += THREADS){
        par[i]        = bo_time[i]; par[128 + i]  = bo_recv[i];
        par[256 + i]  = g1[i];      par[384 + i]  = be1[i];
        par[512 + i]  = g2[i];      par[640 + i]  = be2[i];
        par[768 + i]  = g3[i];      par[896 + i]  = be3[i];
        par[1024 + i] = g4[i];      par[1152 + i] = be4[i];
        par[1280 + i] = b2a[i];     par[1408 + i] = b2b[i];
    }
    for (int i = tid; i < 512; i += THREADS){
        par[1536 + i] = b1a[i];     par[2048 + i] = b1b[i];
    }
    __syncthreads();

    // ---- LN1: v1 = LN(x + bo_time) -> sV (fp32) + sVb (bf16) ----
    const size_t grow = (size_t)blockIdx.x * TILE_R + lrow;
    {
        float4 v[8];
        float s = 0.f, q = 0.f;
#pragma unroll
        for (int i = 0; i < 8; ++i){
            int c = 16 * i + 4 * lq;
            float4 a = *(const float4*)(x + grow * 128 + c);
            a.x += par[c + 0]; a.y += par[c + 1]; a.z += par[c + 2]; a.w += par[c + 3];
            v[i] = a;
            s += a.x + a.y + a.z + a.w;
            q = fmaf(a.x, a.x, q); q = fmaf(a.y, a.y, q);
            q = fmaf(a.z, a.z, q); q = fmaf(a.w, a.w, q);
        }
        s += __shfl_xor_sync(0xffffffffu, s, 1, 4); s += __shfl_xor_sync(0xffffffffu, s, 2, 4);
        q += __shfl_xor_sync(0xffffffffu, q, 1, 4); q += __shfl_xor_sync(0xffffffffu, q, 2, 4);
        float mu = s * 0.0078125f;
        float rs = rsqrtf(q * 0.0078125f - mu * mu + 1e-5f);
#pragma unroll
        for (int i = 0; i < 8; ++i){
            int c = 16 * i + 4 * lq;
            float4 a = v[i], o;
            o.x = (a.x - mu) * rs * par[256 + c + 0] + par[384 + c + 0];
            o.y = (a.y - mu) * rs * par[256 + c + 1] + par[384 + c + 1];
            o.z = (a.z - mu) * rs * par[256 + c + 2] + par[384 + c + 2];
            o.w = (a.w - mu) * rs * par[256 + c + 3] + par[384 + c + 3];
            *(float4*)(sV + lrow * VSTR + c) = o;
            sVb[lrow * VBSTR + (c >> 1)]     = bf2(o.x, o.y);
            sVb[lrow * VBSTR + (c >> 1) + 1] = bf2(o.z, o.w);
        }
    }

    float acc2[2][4][4];
#pragma unroll
    for (int a = 0; a < 2; ++a)
#pragma unroll
        for (int b = 0; b < 4; ++b)
#pragma unroll
            for (int d = 0; d < 4; ++d) acc2[a][b][d] = 0.f;

    // ---- preamble: GEMM1[0] + epilogue -> sH[0] ----
    CP_WAIT(2);          // W1[0] resident
    __syncthreads();     // sVb visible
    {
        float acc1[2][2][4];
        gemm12(acc1, acc2, a1ad, a2ad[0], w1buf[0], w2buf[0], wc, lane, false);
        epi1(acc1, sHbuf[0], par + 1536, wr, wc, qrow, qcol);
    }

    // ---- 16 phases: phase p runs GEMM1[p+1] fused with GEMM2[p] ----
    for (int p = 0; p < 16; ++p){
        __syncthreads();   // sH[p&1] writes visible; frees weight buffers
        if (p <= 14) stage16k(w2addr[(p + 1) & 1], &g_w2img[(p + 1) >> 3][(p + 1) & 7][0], tid);
        if (p <= 13) stage16k(w1addr[p & 1],       &g_w1img[(p + 2) >> 3][(p + 2) & 7][0], tid);
        if (p <= 13)      CP_WAIT(2);
        else if (p == 14) CP_WAIT(1);
        else              CP_WAIT(0);

        const int ch = p & 7;
        if (ch != 7){
            const int q = p + 1;
            float acc1[2][2][4];
            gemm12(acc1, acc2, a1ad, a2ad[p & 1], w1buf[q & 1], w2buf[p & 1],
                   wc, lane, true);
            epi1(acc1, sHbuf[q & 1],
                 par + ((q >= 8) ? 2048 : 1536) + (q & 7) * 64, wr, wc, qrow, qcol);
        } else {
            // boundary: finish this MLP, run LN chain, then start next MLP's GEMM1
            gemm2_only(acc2, a2ad[1], w2buf[1], wc, lane);
            const float* pB2 = par + ((p >= 8) ? 1408 : 1280);
            // T = V + D2 + b2, in place in sV
#pragma unroll
            for (int mt = 0; mt < 2; ++mt){
                const int rb = wr * 32 + mt * 16 + qrow;
#pragma unroll
                for (int ntl = 0; ntl < 4; ++ntl){
                    const int cb = wc * 32 + ntl * 8 + 2 * qcol;
                    const float b20 = pB2[cb], b21 = pB2[cb + 1];
                    float2* v0p = (float2*)(sV + rb * VSTR + cb);
                    float2* v1p = (float2*)(sV + (rb + 8) * VSTR + cb);
                    float2 v0 = *v0p, v1 = *v1p;
                    v0.x += acc2[mt][ntl][0] + b20; v0.y += acc2[mt][ntl][1] + b21;
                    v1.x += acc2[mt][ntl][2] + b20; v1.y += acc2[mt][ntl][3] + b21;
                    *v0p = v0; *v1p = v1;
                }
            }
            __syncthreads();

            // LN on T rows
            float4 v[8];
            float s = 0.f, q = 0.f;
#pragma unroll
            for (int i = 0; i < 8; ++i){
                int c = 16 * i + 4 * lq;
                float4 a = *(const float4*)(sV + lrow * VSTR + c);
                v[i] = a;
                s += a.x + a.y + a.z + a.w;
                q = fmaf(a.x, a.x, q); q = fmaf(a.y, a.y, q);
                q = fmaf(a.z, a.z, q); q = fmaf(a.w, a.w, q);
            }
            s += __shfl_xor_sync(0xffffffffu, s, 1, 4); s += __shfl_xor_sync(0xffffffffu, s, 2, 4);
            q += __shfl_xor_sync(0xffffffffu, q, 1, 4); q += __shfl_xor_sync(0xffffffffu, q, 2, 4);
            float mu = s * 0.0078125f;
            float rs = rsqrtf(q * 0.0078125f - mu * mu + 1e-5f);

            if (p == 7){
                float s2 = 0.f, q2 = 0.f;
#pragma unroll
                for (int i = 0; i < 8; ++i){
                    int c = 16 * i + 4 * lq;
                    float4 a = v[i], o;
                    o.x = (a.x - mu) * rs * par[512 + c + 0] + par[640 + c + 0] + par[128 + c + 0];
                    o.y = (a.y - mu) * rs * par[512 + c + 1] + par[640 + c + 1] + par[128 + c + 1];
                    o.z = (a.z - mu) * rs * par[512 + c + 2] + par[640 + c + 2] + par[128 + c + 2];
                    o.w = (a.w - mu) * rs * par[512 + c + 3] + par[640 + c + 3] + par[128 + c + 3];
                    v[i] = o;
                    s2 += o.x + o.y + o.z + o.w;
                    q2 = fmaf(o.x, o.x, q2); q2 = fmaf(o.y, o.y, q2);
                    q2 = fmaf(o.z, o.z, q2); q2 = fmaf(o.w, o.w, q2);
                }
                s2 += __shfl_xor_sync(0xffffffffu, s2, 1, 4); s2 += __shfl_xor_sync(0xffffffffu, s2, 2, 4);
                q2 += __shfl_xor_sync(0xffffffffu, q2, 1, 4); q2 += __shfl_xor_sync(0xffffffffu, q2, 2, 4);
                float mu2 = s2 * 0.0078125f;
                float rs2 = rsqrtf(q2 * 0.0078125f - mu2 * mu2 + 1e-5f);
#pragma unroll
                for (int i = 0; i < 8; ++i){
                    int c = 16 * i + 4 * lq;
                    float4 a = v[i], o;
                    o.x = (a.x - mu2) * rs2 * par[768 + c + 0] + par[896 + c + 0];
                    o.y = (a.y - mu2) * rs2 * par[768 + c + 1] + par[896 + c + 1];
                    o.z = (a.z - mu2) * rs2 * par[768 + c + 2] + par[896 + c + 2];
                    o.w = (a.w - mu2) * rs2 * par[768 + c + 3] + par[896 + c + 3];
                    *(float4*)(sV + lrow * VSTR + c) = o;
                    sVb[lrow * VBSTR + (c >> 1)]     = bf2(o.x, o.y);
                    sVb[lrow * VBSTR + (c >> 1) + 1] = bf2(o.z, o.w);
                }
                __syncthreads();   // sVb ready for mlp1's GEMM1

#pragma unroll
                for (int a = 0; a < 2; ++a)
#pragma unroll
                    for (int b = 0; b < 4; ++b)
#pragma unroll
                        for (int d = 0; d < 4; ++d) acc2[a][b][d] = 0.f;
                float acc1[2][2][4];
                gemm12(acc1, acc2, a1ad, a2ad[0], w1buf[0], w2buf[0], wc, lane, false);
                epi1(acc1, sHbuf[0], par + 2048, wr, wc, qrow, qcol);
            } else {
                // p == 15: out = LN4(T) -> GMEM
#pragma unroll
                for (int i = 0; i < 8; ++i){
                    int c = 16 * i + 4 * lq;
                    float4 a = v[i], o;
                    o.x = (a.x - mu) * rs * par[1024 + c + 0] + par[1152 + c + 0];
                    o.y = (a.y - mu) * rs * par[1024 + c + 1] + par[1152 + c + 1];
                    o.z = (a.z - mu) * rs * par[1024 + c + 2] + par[1152 + c + 2];
                    o.w = (a.w - mu) * rs * par[1024 + c + 3] + par[1152 + c + 3];
                    *(float4*)(out + grow * 128 + c) = o;
                }
            }
        }
    }
}

extern "C" void kernel_launch(void* const* d_in, const int* in_sizes, int n_in,
                              void* d_out, int out_size)
{
    const float* x       = (const float*)d_in[0];
    // d_in[1]=router (dead), d_in[3]=bo_send (dead)
    const float* bo_time = (const float*)d_in[2];
    const float* bo_recv = (const float*)d_in[4];
    const float* g1 = (const float*)d_in[5],  *be1 = (const float*)d_in[6];
    const float* g2 = (const float*)d_in[7],  *be2 = (const float*)d_in[8];
    const float* g3 = (const float*)d_in[9],  *be3 = (const float*)d_in[10];
    const float* g4 = (const float*)d_in[11], *be4 = (const float*)d_in[12];
    const float* W1a = (const float*)d_in[13], *b1a = (const float*)d_in[14];
    const float* W2a = (const float*)d_in[15], *b2a = (const float*)d_in[16];
    const float* W1b = (const float*)d_in[17], *b1b = (const float*)d_in[18];
    const float* W2b = (const float*)d_in[19], *b2b = (const float*)d_in[20];
    float* out = (float*)d_out;

    int rows   = in_sizes[0] / 128;   // 131072
    int blocks = rows / TILE_R;       // 1024

    prep_kernel<<<256, 256>>>(W1a, W2a, W1b, W2b);

    cudaFuncSetAttribute(tsal_ldsm_kernel,
                         cudaFuncAttributeMaxDynamicSharedMemorySize, SMEM_BYTES);
    tsal_ldsm_kernel<<<blocks, THREADS, SMEM_BYTES>>>(
        x, bo_time, bo_recv,
        g1, be1, g2, be2, g3, be3, g4, be4,
        b1a, b2a, b1b, b2b, out);
}